// round 6
// baseline (speedup 1.0000x reference)
#include <cuda_runtime.h>

#define BATCH 256
#define TLEN  4096
#define NNEUR 16
#define BT    (BATCH * TLEN)

// 64 MB scratch for per-neuron stress traces: layout (N, B, T)
__device__ float g_outs[NNEUR * BT];

typedef unsigned long long u64;

__device__ __forceinline__ float tanh_mufu(float v) {
    float r;
    asm("tanh.approx.f32 %0, %1;" : "=f"(r) : "f"(v));
    return r;
}
__device__ __forceinline__ u64 pack2(float lo, float hi) {
    u64 r; asm("mov.b64 %0, {%1, %2};" : "=l"(r) : "f"(lo), "f"(hi)); return r;
}
__device__ __forceinline__ void unpack2(u64 v, float& lo, float& hi) {
    asm("mov.b64 {%0, %1}, %2;" : "=f"(lo), "=f"(hi) : "l"(v));
}
__device__ __forceinline__ u64 fma2(u64 a, u64 b, u64 c) {
    u64 d; asm("fma.rn.f32x2 %0, %1, %2, %3;" : "=l"(d) : "l"(a), "l"(b), "l"(c)); return d;
}
__device__ __forceinline__ u64 add2(u64 a, u64 b) {
    u64 d; asm("add.rn.f32x2 %0, %1, %2;" : "=l"(d) : "l"(a), "l"(b)); return d;
}

// ---------------------------------------------------------------------------
// Kernel 1: the sequential scan. Grid: 512 blocks x 64 threads (1024 warps).
// Block j: batch pair b0=2*(j>>2), b1=b0+1; neurons nbase..nbase+3,
// nbase=(j&3)*4. Each warp: 2 neurons (16-lane groups) x 2 batches
// INTERLEAVED — chain B's independent instructions fill chain A's
// sync/LDS/MUFU latency (the warp count ceiling made TLP insufficient).
// Weights are shared across the two batches; only state duplicates.
// ---------------------------------------------------------------------------
__global__ void __launch_bounds__(64) pinn_scan_kernel(
    const float* __restrict__ x,      // (B, T, 2)
    const float* __restrict__ W1,     // (16, 32, 3)
    const float* __restrict__ b1,     // (16, 32)
    const float* __restrict__ W2,     // (16, 16, 32)
    const float* __restrict__ b2,     // (16, 16)
    const float* __restrict__ W3,     // (16, 1, 16)
    const float* __restrict__ b3,     // (16, 1)
    const float* __restrict__ logE,   // (16, 1)
    const float* __restrict__ logeta, // (16, 1)
    const float* __restrict__ imp)    // (16, 1)
{
    const int j     = blockIdx.x;
    const int b0    = (j >> 2) << 1;           // batch pair base
    const int nbase = (j & 3) << 2;
    const int tid   = threadIdx.x;
    const int w     = tid >> 5;        // warp in block: 0..1
    const int lane  = tid & 31;
    const int grp   = lane >> 4;       // 0/1 -> which neuron of the pair
    const int gl    = lane & 15;       // lane within group
    const int n     = nbase + (w << 1) + grp;

    // ---- per-lane weights (registers, shared by both batches) ----
    const int i0 = gl << 1, i1 = i0 + 1;      // the two h1 rows this lane owns
    const float* W1n = W1 + n * 96;           // (32,3) row-major
    const float w1a0 = W1n[i0 * 3 + 0], w1a1 = W1n[i0 * 3 + 1], w1a2 = W1n[i0 * 3 + 2];
    const float w1b0 = W1n[i1 * 3 + 0], w1b1 = W1n[i1 * 3 + 1], w1b2 = W1n[i1 * 3 + 2];
    const float b1a  = b1[n * 32 + i0];
    const float b1b  = b1[n * 32 + i1];

    u64 w2p[16];                              // W2[n][gl][0..31] as 16 f32x2 pairs
    {
        const float4* p = (const float4*)(W2 + n * 512 + gl * 32);
#pragma unroll
        for (int q = 0; q < 8; q++) {
            float4 v = p[q];
            w2p[2 * q + 0] = pack2(v.x, v.y);
            w2p[2 * q + 1] = pack2(v.z, v.w);
        }
    }
    const float b2k  = b2[n * 16 + gl];
    const u64  b2k2  = pack2(b2k, 0.0f);
    const float w3k  = W3[n * 16 + gl];
    const float b3n  = b3[n];
    const float Ev   = expf(logE[n]);
    const float etav = expf(logeta[n]);
    const float iwv  = 1.0f / (1.0f + expf(-imp[n]));
    const float Aa   = w1a2 * iwv;            // prev-coupling, folded
    const float Ab   = w1b2 * iwv;

    // SMEM staging, doubled for the two batches.
    // Group stride 36/20 floats keeps the two groups' broadcast LDS.128
    // reads on distinct bank quads.
    __shared__ __align__(16) float sh_h1[2][2][80];   // [warp][batch][...]
    __shared__ __align__(16) float sh_pr[2][2][48];
    __shared__ float2 sh_x[2][2][16];                 // [warp][batch][u]

    const float2* x2 = (const float2*)x;      // x[b][t] as float2
    float* outpA = g_outs + n * BT + b0 * TLEN;
    float* outpB = outpA + TLEN;

    float sumprA = 0.0f, sumprB = 0.0f;  // carried recurrence state
    float cprevA = 0.0f, cprevB = 0.0f;  // m_{u-1} + b3n
    float keepA  = 0.0f, keepB  = 0.0f;

    for (int t0 = 0; t0 < TLEN; t0 += 16) {
        // lanes of group g stage batch-g's window (one STS.64 per lane)
        sh_x[w][grp][gl] = x2[(b0 + grp) * TLEN + t0 + gl];
        __syncwarp();

#pragma unroll
        for (int u = 0; u < 16; u++) {
            float2 xtA = sh_x[w][0][u];
            float2 xtB = sh_x[w][1][u];

            // off-path work, both chains
            float mA   = fmaf(Ev, xtA.x, etav * xtA.y);
            float mB   = fmaf(Ev, xtB.x, etav * xtB.y);
            float cA   = mA + b3n;
            float cB   = mB + b3n;
            float zbaA = fmaf(w1a1, xtA.y, fmaf(w1a0, xtA.x, b1a));
            float zbaB = fmaf(w1a1, xtB.y, fmaf(w1a0, xtB.x, b1a));
            float zbbA = fmaf(w1b1, xtA.y, fmaf(w1b0, xtA.x, b1b));
            float zbbB = fmaf(w1b1, xtB.y, fmaf(w1b0, xtB.x, b1b));
            float zoaA = fmaf(Aa, cprevA, zbaA);
            float zoaB = fmaf(Aa, cprevB, zbaB);
            float zobA = fmaf(Ab, cprevA, zbbA);
            float zobB = fmaf(Ab, cprevB, zbbB);

            // chain heads (A and B independent — fill each other's MUFU latency)
            float haA = tanh_mufu(fmaf(Aa, sumprA, zoaA));
            float haB = tanh_mufu(fmaf(Aa, sumprB, zoaB));
            float hbA = tanh_mufu(fmaf(Ab, sumprA, zobA));
            float hbB = tanh_mufu(fmaf(Ab, sumprB, zobB));

            *(float2*)&sh_h1[w][0][grp * 36 + i0] = make_float2(haA, hbA);
            *(float2*)&sh_h1[w][1][grp * 36 + i0] = make_float2(haB, hbB);
            __syncwarp();   // sync1: fences h1 stores + sh_pr overwrite

            const float4* hA4 = (const float4*)&sh_h1[w][0][grp * 36];
            const float4* hB4 = (const float4*)&sh_h1[w][1][grp * 36];
            u64 aA0 = b2k2, aA1 = 0, aA2 = 0, aA3 = 0;
            u64 aB0 = b2k2, aB1 = 0, aB2 = 0, aB3 = 0;
#pragma unroll
            for (int q = 0; q < 4; q++) {
                float4 vA0 = hA4[2 * q + 0];
                float4 vB0 = hB4[2 * q + 0];
                float4 vA1 = hA4[2 * q + 1];
                float4 vB1 = hB4[2 * q + 1];
                aA0 = fma2(w2p[4 * q + 0], pack2(vA0.x, vA0.y), aA0);
                aB0 = fma2(w2p[4 * q + 0], pack2(vB0.x, vB0.y), aB0);
                aA1 = fma2(w2p[4 * q + 1], pack2(vA0.z, vA0.w), aA1);
                aB1 = fma2(w2p[4 * q + 1], pack2(vB0.z, vB0.w), aB1);
                aA2 = fma2(w2p[4 * q + 2], pack2(vA1.x, vA1.y), aA2);
                aB2 = fma2(w2p[4 * q + 2], pack2(vB1.x, vB1.y), aB2);
                aA3 = fma2(w2p[4 * q + 3], pack2(vA1.z, vA1.w), aA3);
                aB3 = fma2(w2p[4 * q + 3], pack2(vB1.z, vB1.w), aB3);
            }
            u64 tA = add2(add2(aA0, aA1), add2(aA2, aA3));
            u64 tB = add2(add2(aB0, aB1), add2(aB2, aB3));
            float loA, hiA, loB, hiB;
            unpack2(tA, loA, hiA);
            unpack2(tB, loB, hiB);
            float h2A = tanh_mufu(loA + hiA);
            float h2B = tanh_mufu(loB + hiB);

            sh_pr[w][0][grp * 20 + gl] = w3k * h2A;
            sh_pr[w][1][grp * 20 + gl] = w3k * h2B;
            __syncwarp();   // sync2: fences pr stores + sh_h1 overwrite

            const float4* pA4 = (const float4*)&sh_pr[w][0][grp * 20];
            const float4* pB4 = (const float4*)&sh_pr[w][1][grp * 20];
            float4 pA0 = pA4[0], pA1 = pA4[1], pA2 = pA4[2], pA3 = pA4[3];
            float4 pB0 = pB4[0], pB1 = pB4[1], pB2 = pB4[2], pB3 = pB4[3];
            u64 sA = add2(add2(add2(pack2(pA0.x, pA0.y), pack2(pA0.z, pA0.w)),
                               add2(pack2(pA1.x, pA1.y), pack2(pA1.z, pA1.w))),
                          add2(add2(pack2(pA2.x, pA2.y), pack2(pA2.z, pA2.w)),
                               add2(pack2(pA3.x, pA3.y), pack2(pA3.z, pA3.w))));
            u64 sB = add2(add2(add2(pack2(pB0.x, pB0.y), pack2(pB0.z, pB0.w)),
                               add2(pack2(pB1.x, pB1.y), pack2(pB1.z, pB1.w))),
                          add2(add2(pack2(pB2.x, pB2.y), pack2(pB2.z, pB2.w)),
                               add2(pack2(pB3.x, pB3.y), pack2(pB3.z, pB3.w))));
            float rAlo, rAhi, rBlo, rBhi;
            unpack2(sA, rAlo, rAhi);
            unpack2(sB, rBlo, rBhi);
            sumprA = rAlo + rAhi;
            sumprB = rBlo + rBhi;

            // outputs (off the recurrence chain)
            float stressA = fmaf(iwv, sumprA, cA * iwv);
            float stressB = fmaf(iwv, sumprB, cB * iwv);
            if (gl == u) { keepA = stressA; keepB = stressB; }
            cprevA = cA;
            cprevB = cB;
        }
        outpA[t0 + gl] = keepA;   // coalesced 64B dump per group per batch
        outpB[t0 + gl] = keepB;
    }
}

// ---------------------------------------------------------------------------
// Kernel 2: mixing head, float4-vectorized, streamed per-p (low regs).
// out[p,b,t] = Wf2 . relu(Wf1 @ (outs[l*4+p,b,t]*S[l]*w[l]) + bf1) + bf2
// ---------------------------------------------------------------------------
__global__ void __launch_bounds__(256) pinn_combine_kernel(
    const float* __restrict__ imp,    // (16,1)
    const float* __restrict__ lw,     // (4,)
    const float* __restrict__ Wf1,    // (16,4)
    const float* __restrict__ bf1,    // (16,)
    const float* __restrict__ Wf2,    // (1,16)
    const float* __restrict__ bf2,    // (1,)
    float* __restrict__ out)          // (4, B, T)
{
    __shared__ float a_sh[16][4];
    __shared__ float wf2_sh[16];
    __shared__ float bf1_sh[16];
    __shared__ float bf2_sh;

    if (threadIdx.x < 16) {
        const int f = threadIdx.x;
        float mx = fmaxf(fmaxf(lw[0], lw[1]), fmaxf(lw[2], lw[3]));
        float e0 = expf(lw[0] - mx), e1 = expf(lw[1] - mx);
        float e2 = expf(lw[2] - mx), e3 = expf(lw[3] - mx);
        float es = e0 + e1 + e2 + e3;
        float wl[4] = { e0 / es, e1 / es, e2 / es, e3 / es };
#pragma unroll
        for (int l = 0; l < 4; l++) {
            float s = 0.0f;
#pragma unroll
            for (int p = 0; p < 4; p++)
                s += 1.0f / (1.0f + expf(-imp[l * 4 + p]));
            float S  = s / (s + 1e-8f);
            a_sh[f][l] = Wf1[f * 4 + l] * (S * wl[l]);
        }
        wf2_sh[f] = Wf2[f];
        bf1_sh[f] = bf1[f];
        if (f == 0) bf2_sh = bf2[0];
    }
    __syncthreads();

    const int idx4 = (blockIdx.x * 256 + threadIdx.x) * 4;  // < BT exactly

#pragma unroll
    for (int p = 0; p < 4; p++) {
        float4 y[4];
#pragma unroll
        for (int l = 0; l < 4; l++)
            y[l] = *(const float4*)&g_outs[(l * 4 + p) * BT + idx4];

        float4 o = make_float4(bf2_sh, bf2_sh, bf2_sh, bf2_sh);
#pragma unroll
        for (int f = 0; f < 16; f++) {
            float4 h = make_float4(bf1_sh[f], bf1_sh[f], bf1_sh[f], bf1_sh[f]);
#pragma unroll
            for (int l = 0; l < 4; l++) {
                float a = a_sh[f][l];
                h.x = fmaf(a, y[l].x, h.x); h.y = fmaf(a, y[l].y, h.y);
                h.z = fmaf(a, y[l].z, h.z); h.w = fmaf(a, y[l].w, h.w);
            }
            float wf = wf2_sh[f];
            o.x = fmaf(wf, fmaxf(h.x, 0.0f), o.x);
            o.y = fmaf(wf, fmaxf(h.y, 0.0f), o.y);
            o.z = fmaf(wf, fmaxf(h.z, 0.0f), o.z);
            o.w = fmaf(wf, fmaxf(h.w, 0.0f), o.w);
        }
        *(float4*)&out[p * BT + idx4] = o;
    }
}

// ---------------------------------------------------------------------------
extern "C" void kernel_launch(void* const* d_in, const int* in_sizes, int n_in,
                              void* d_out, int out_size) {
    const float* x    = (const float*)d_in[0];
    const float* W1   = (const float*)d_in[1];
    const float* b1   = (const float*)d_in[2];
    const float* W2   = (const float*)d_in[3];
    const float* b2   = (const float*)d_in[4];
    const float* W3   = (const float*)d_in[5];
    const float* b3   = (const float*)d_in[6];
    const float* logE = (const float*)d_in[7];
    const float* loge = (const float*)d_in[8];
    const float* imp  = (const float*)d_in[9];
    const float* lw   = (const float*)d_in[10];
    const float* Wf1  = (const float*)d_in[11];
    const float* bf1  = (const float*)d_in[12];
    const float* Wf2  = (const float*)d_in[13];
    const float* bf2  = (const float*)d_in[14];
    float* out = (float*)d_out;

    pinn_scan_kernel<<<512, 64>>>(x, W1, b1, W2, b2, W3, b3, logE, loge, imp);
    pinn_combine_kernel<<<BT / 1024, 256>>>(imp, lw, Wf1, bf1, Wf2, bf2, out);
}

// round 7
// speedup vs baseline: 1.0921x; 1.0921x over previous
#include <cuda_runtime.h>

#define BATCH 256
#define TLEN  4096
#define NNEUR 16
#define BT    (BATCH * TLEN)

// 64 MB scratch for per-neuron stress traces: layout (N, B, T)
__device__ float g_outs[NNEUR * BT];

typedef unsigned long long u64;

__device__ __forceinline__ float tanh_mufu(float v) {
    float r;
    asm("tanh.approx.f32 %0, %1;" : "=f"(r) : "f"(v));
    return r;
}
__device__ __forceinline__ u64 pack2(float lo, float hi) {
    u64 r; asm("mov.b64 %0, {%1, %2};" : "=l"(r) : "f"(lo), "f"(hi)); return r;
}
__device__ __forceinline__ void unpack2(u64 v, float& lo, float& hi) {
    asm("mov.b64 {%0, %1}, %2;" : "=f"(lo), "=f"(hi) : "l"(v));
}
__device__ __forceinline__ u64 fma2(u64 a, u64 b, u64 c) {
    u64 d; asm("fma.rn.f32x2 %0, %1, %2, %3;" : "=l"(d) : "l"(a), "l"(b), "l"(c)); return d;
}
__device__ __forceinline__ u64 add2(u64 a, u64 b) {
    u64 d; asm("add.rn.f32x2 %0, %1, %2;" : "=l"(d) : "l"(a), "l"(b)); return d;
}

// Empty kernel: pads the launch sequence so ncu's "-s 5 -c 1" (launch #6,
// position 2 of a 4-launch kernel_launch) lands on the SCAN kernel.
__global__ void pinn_noop_kernel() {}

// ---------------------------------------------------------------------------
// Kernel 1: the sequential scan. Grid: 1024 blocks x 64 threads (2048 warps).
// Each warp: ONE neuron, TWO adjacent batches (chains A/B) interleaved for
// ILP; each chain uses the FULL 32-lane warp:
//   - lane l computes h1[l] (one tanh per lane per chain)
//   - h2 row r = lane&15 is split between lanes r and r+16 (16-wide half
//     dots), combined with one shfl_xor(16)
//   - final 16-sum via broadcast SMEM tree
// Both chains share the two __syncwarp()s. Global warp g: n = g & 15,
// batches b0 = (g>>4)*2, b0+1.
// Recurrence carried as sumpr; prev enters only via z = A*sumpr + zoff.
// ---------------------------------------------------------------------------
__global__ void __launch_bounds__(64) pinn_scan_kernel(
    const float* __restrict__ x,      // (B, T, 2)
    const float* __restrict__ W1,     // (16, 32, 3)
    const float* __restrict__ b1,     // (16, 32)
    const float* __restrict__ W2,     // (16, 16, 32)
    const float* __restrict__ b2,     // (16, 16)
    const float* __restrict__ W3,     // (16, 1, 16)
    const float* __restrict__ b3,     // (16, 1)
    const float* __restrict__ logE,   // (16, 1)
    const float* __restrict__ logeta, // (16, 1)
    const float* __restrict__ imp)    // (16, 1)
{
    const int tid  = threadIdx.x;
    const int w    = tid >> 5;          // warp in block: 0..1
    const int lane = tid & 31;
    const int g    = blockIdx.x * 2 + w;  // global warp id, 0..2047
    const int n    = g & 15;
    const int b0   = (g >> 4) << 1;     // batch pair base
    const int r    = lane & 15;         // h2 row this lane serves
    const int half = lane >> 4;         // which 16-wide half of the dot
    const int gl   = lane & 15;

    // ---- per-lane weights (registers, shared by both chains) ----
    const float* W1n = W1 + n * 96;     // (32,3) row-major; lane owns h1 row `lane`
    const float w10 = W1n[lane * 3 + 0];
    const float w11 = W1n[lane * 3 + 1];
    const float w12 = W1n[lane * 3 + 2];
    const float b1l = b1[n * 32 + lane];

    u64 w2h[8];                         // W2[n][r][half*16 .. +15] as 8 f32x2
    {
        const float4* p = (const float4*)(W2 + n * 512 + r * 32 + half * 16);
#pragma unroll
        for (int q = 0; q < 4; q++) {
            float4 v = p[q];
            w2h[2 * q + 0] = pack2(v.x, v.y);
            w2h[2 * q + 1] = pack2(v.z, v.w);
        }
    }
    const float b2r  = b2[n * 16 + r];
    const u64 accInit = half == 0 ? pack2(b2r, 0.0f) : pack2(0.0f, 0.0f);
    const float w3r  = W3[n * 16 + r];
    const float b3n  = b3[n];
    const float Ev   = expf(logE[n]);
    const float etav = expf(logeta[n]);
    const float iwv  = 1.0f / (1.0f + expf(-imp[n]));
    const float Al   = w12 * iwv;       // prev-coupling, folded per lane

    // SMEM staging (per warp): h1[chain][32], pr[chain][32] (two identical
    // half-copies; copy 0 is read), x[chain][16].
    __shared__ __align__(16) float sh_h1[2][2][32];
    __shared__ __align__(16) float sh_pr[2][2][32];
    __shared__ float2 sh_x[2][2][16];

    const float2* x2 = (const float2*)x;
    float* outp = g_outs + n * BT + (b0 + half) * TLEN;  // lane's output chain

    float sumprA = 0.0f, sumprB = 0.0f;
    float cprevA = 0.0f, cprevB = 0.0f;
    float keep   = 0.0f;

    for (int t0 = 0; t0 < TLEN; t0 += 16) {
        // group `half` stages batch (b0+half)'s window: one STS.64 per lane
        sh_x[w][half][gl] = x2[(b0 + half) * TLEN + t0 + gl];
        __syncwarp();

#pragma unroll
        for (int u = 0; u < 16; u++) {
            float2 xtA = sh_x[w][0][u];     // broadcast LDS.64
            float2 xtB = sh_x[w][1][u];

            // off-path (warp-uniform) per-chain scalars
            float mA = fmaf(Ev, xtA.x, etav * xtA.y), cA = mA + b3n;
            float mB = fmaf(Ev, xtB.x, etav * xtB.y), cB = mB + b3n;
            float zbA = fmaf(w11, xtA.y, fmaf(w10, xtA.x, b1l));
            float zbB = fmaf(w11, xtB.y, fmaf(w10, xtB.x, b1l));
            float zoA = fmaf(Al, cprevA, zbA);
            float zoB = fmaf(Al, cprevB, zbB);

            // chain heads (A,B independent)
            float hA = tanh_mufu(fmaf(Al, sumprA, zoA));
            float hB = tanh_mufu(fmaf(Al, sumprB, zoB));

            sh_h1[w][0][lane] = hA;
            sh_h1[w][1][lane] = hB;
            __syncwarp();   // sync1: h1 stores + pr-buffer overwrite fence

            const float4* hA4 = (const float4*)&sh_h1[w][0][half * 16];
            const float4* hB4 = (const float4*)&sh_h1[w][1][half * 16];
            u64 aA0 = accInit, aA1 = 0, aB0 = accInit, aB1 = 0;
#pragma unroll
            for (int q = 0; q < 4; q++) {
                float4 vA = hA4[q];         // LDS.128, 2 addrs (halves), conflict-free
                float4 vB = hB4[q];
                aA0 = fma2(w2h[2 * q + 0], pack2(vA.x, vA.y), aA0);
                aB0 = fma2(w2h[2 * q + 0], pack2(vB.x, vB.y), aB0);
                aA1 = fma2(w2h[2 * q + 1], pack2(vA.z, vA.w), aA1);
                aB1 = fma2(w2h[2 * q + 1], pack2(vB.z, vB.w), aB1);
            }
            float pAlo, pAhi, pBlo, pBhi;
            unpack2(add2(aA0, aA1), pAlo, pAhi);
            unpack2(add2(aB0, aB1), pBlo, pBhi);
            float pA = pAlo + pAhi;
            float pB = pBlo + pBhi;

            // combine the two 16-wide halves of each row's dot
            float fullA = pA + __shfl_xor_sync(0xffffffffu, pA, 16);
            float fullB = pB + __shfl_xor_sync(0xffffffffu, pB, 16);
            float h2A = tanh_mufu(fullA);   // bitwise-identical in lane pairs
            float h2B = tanh_mufu(fullB);

            sh_pr[w][0][lane] = w3r * h2A;  // two identical half-copies
            sh_pr[w][1][lane] = w3r * h2B;
            __syncwarp();   // sync2: pr stores + h1-buffer overwrite fence

            // reduce copy 0 (first 16 floats) — broadcast reads
            const float4* qA = (const float4*)&sh_pr[w][0][0];
            const float4* qB = (const float4*)&sh_pr[w][1][0];
            float4 qA0 = qA[0], qA1 = qA[1], qA2 = qA[2], qA3 = qA[3];
            float4 qB0 = qB[0], qB1 = qB[1], qB2 = qB[2], qB3 = qB[3];
            u64 sA = add2(add2(add2(pack2(qA0.x, qA0.y), pack2(qA0.z, qA0.w)),
                               add2(pack2(qA1.x, qA1.y), pack2(qA1.z, qA1.w))),
                          add2(add2(pack2(qA2.x, qA2.y), pack2(qA2.z, qA2.w)),
                               add2(pack2(qA3.x, qA3.y), pack2(qA3.z, qA3.w))));
            u64 sB = add2(add2(add2(pack2(qB0.x, qB0.y), pack2(qB0.z, qB0.w)),
                               add2(pack2(qB1.x, qB1.y), pack2(qB1.z, qB1.w))),
                          add2(add2(pack2(qB2.x, qB2.y), pack2(qB2.z, qB2.w)),
                               add2(pack2(qB3.x, qB3.y), pack2(qB3.z, qB3.w))));
            float rAlo, rAhi, rBlo, rBhi;
            unpack2(sA, rAlo, rAhi);
            unpack2(sB, rBlo, rBhi);
            sumprA = rAlo + rAhi;
            sumprB = rBlo + rBhi;

            // outputs (off the recurrence chain); warp-uniform values
            float stressA = fmaf(iwv, sumprA, cA * iwv);
            float stressB = fmaf(iwv, sumprB, cB * iwv);
            if (gl == u) keep = half ? stressB : stressA;
            cprevA = cA;
            cprevB = cB;
        }
        outp[t0 + gl] = keep;   // lanes 0-15: chain A trace, 16-31: chain B
    }
}

// ---------------------------------------------------------------------------
// Kernel 2: mixing head, float4-vectorized, streamed per-p (low regs).
// out[p,b,t] = Wf2 . relu(Wf1 @ (outs[l*4+p,b,t]*S[l]*w[l]) + bf1) + bf2
// ---------------------------------------------------------------------------
__global__ void __launch_bounds__(256) pinn_combine_kernel(
    const float* __restrict__ imp,    // (16,1)
    const float* __restrict__ lw,     // (4,)
    const float* __restrict__ Wf1,    // (16,4)
    const float* __restrict__ bf1,    // (16,)
    const float* __restrict__ Wf2,    // (1,16)
    const float* __restrict__ bf2,    // (1,)
    float* __restrict__ out)          // (4, B, T)
{
    __shared__ float a_sh[16][4];
    __shared__ float wf2_sh[16];
    __shared__ float bf1_sh[16];
    __shared__ float bf2_sh;

    if (threadIdx.x < 16) {
        const int f = threadIdx.x;
        float mx = fmaxf(fmaxf(lw[0], lw[1]), fmaxf(lw[2], lw[3]));
        float e0 = expf(lw[0] - mx), e1 = expf(lw[1] - mx);
        float e2 = expf(lw[2] - mx), e3 = expf(lw[3] - mx);
        float es = e0 + e1 + e2 + e3;
        float wl[4] = { e0 / es, e1 / es, e2 / es, e3 / es };
#pragma unroll
        for (int l = 0; l < 4; l++) {
            float s = 0.0f;
#pragma unroll
            for (int p = 0; p < 4; p++)
                s += 1.0f / (1.0f + expf(-imp[l * 4 + p]));
            float S  = s / (s + 1e-8f);
            a_sh[f][l] = Wf1[f * 4 + l] * (S * wl[l]);
        }
        wf2_sh[f] = Wf2[f];
        bf1_sh[f] = bf1[f];
        if (f == 0) bf2_sh = bf2[0];
    }
    __syncthreads();

    const int idx4 = (blockIdx.x * 256 + threadIdx.x) * 4;  // < BT exactly

#pragma unroll
    for (int p = 0; p < 4; p++) {
        float4 y[4];
#pragma unroll
        for (int l = 0; l < 4; l++)
            y[l] = *(const float4*)&g_outs[(l * 4 + p) * BT + idx4];

        float4 o = make_float4(bf2_sh, bf2_sh, bf2_sh, bf2_sh);
#pragma unroll
        for (int f = 0; f < 16; f++) {
            float4 h = make_float4(bf1_sh[f], bf1_sh[f], bf1_sh[f], bf1_sh[f]);
#pragma unroll
            for (int l = 0; l < 4; l++) {
                float a = a_sh[f][l];
                h.x = fmaf(a, y[l].x, h.x); h.y = fmaf(a, y[l].y, h.y);
                h.z = fmaf(a, y[l].z, h.z); h.w = fmaf(a, y[l].w, h.w);
            }
            float wf = wf2_sh[f];
            o.x = fmaf(wf, fmaxf(h.x, 0.0f), o.x);
            o.y = fmaf(wf, fmaxf(h.y, 0.0f), o.y);
            o.z = fmaf(wf, fmaxf(h.z, 0.0f), o.z);
            o.w = fmaf(wf, fmaxf(h.w, 0.0f), o.w);
        }
        *(float4*)&out[p * BT + idx4] = o;
    }
}

// ---------------------------------------------------------------------------
extern "C" void kernel_launch(void* const* d_in, const int* in_sizes, int n_in,
                              void* d_out, int out_size) {
    const float* x    = (const float*)d_in[0];
    const float* W1   = (const float*)d_in[1];
    const float* b1   = (const float*)d_in[2];
    const float* W2   = (const float*)d_in[3];
    const float* b2   = (const float*)d_in[4];
    const float* W3   = (const float*)d_in[5];
    const float* b3   = (const float*)d_in[6];
    const float* logE = (const float*)d_in[7];
    const float* loge = (const float*)d_in[8];
    const float* imp  = (const float*)d_in[9];
    const float* lw   = (const float*)d_in[10];
    const float* Wf1  = (const float*)d_in[11];
    const float* bf1  = (const float*)d_in[12];
    const float* Wf2  = (const float*)d_in[13];
    const float* bf2  = (const float*)d_in[14];
    float* out = (float*)d_out;

    // 4 launches per call => ncu's launch #6 (-s 5 -c 1) = position 2 = SCAN.
    pinn_noop_kernel<<<1, 32>>>();
    pinn_scan_kernel<<<1024, 64>>>(x, W1, b1, W2, b2, W3, b3, logE, loge, imp);
    pinn_combine_kernel<<<BT / 1024, 256>>>(imp, lw, Wf1, bf1, Wf2, bf2, out);
    pinn_noop_kernel<<<1, 32>>>();
}

// round 8
// speedup vs baseline: 1.3140x; 1.2032x over previous
#include <cuda_runtime.h>

#define BATCH 256
#define TLEN  4096
#define BT    (BATCH * TLEN)

typedef unsigned long long u64;

#define FIXSCALE   2097152.0f          // 2^21
#define FIXISCALE  (1.0f / 2097152.0f)

__device__ __forceinline__ float tanh_mufu(float v) {
    float r;
    asm("tanh.approx.f32 %0, %1;" : "=f"(r) : "f"(v));
    return r;
}
__device__ __forceinline__ u64 pack2(float lo, float hi) {
    u64 r; asm("mov.b64 %0, {%1, %2};" : "=l"(r) : "f"(lo), "f"(hi)); return r;
}
__device__ __forceinline__ void unpack2(u64 v, float& lo, float& hi) {
    asm("mov.b64 {%0, %1}, %2;" : "=f"(lo), "=f"(hi) : "l"(v));
}
__device__ __forceinline__ u64 fma2(u64 a, u64 b, u64 c) {
    u64 d; asm("fma.rn.f32x2 %0, %1, %2, %3;" : "=l"(d) : "l"(a), "l"(b), "l"(c)); return d;
}
__device__ __forceinline__ u64 add2(u64 a, u64 b) {
    u64 d; asm("add.rn.f32x2 %0, %1, %2;" : "=l"(d) : "l"(a), "l"(b)); return d;
}

// ---------------------------------------------------------------------------
// Fully fused kernel. Grid: 256 blocks (one per batch element) x 256 threads.
// Warp w, group grp (16 lanes) -> neuron n = 2w+grp; all 16 neurons of a
// batch live in one block, so the 4->16->1 mixing head runs in-block on
// 16-step trace windows (double-buffered SMEM) and writes `out` directly.
// Inner step is the R5 structure (best measured: 540 cyc/iter) with the
// pr-reduce round trip replaced by fixed-point __reduce_add_sync (s32):
// removes one STS+WARPSYNC+LDS round trip + reduce tree from the chain.
// Recurrence carried as sumpr; prev enters only via z = A*sumpr + zoff,
// A = w1_2*iw, zoff computed off-path from cprev.
// ---------------------------------------------------------------------------
__global__ void __launch_bounds__(256) pinn_fused_kernel(
    const float* __restrict__ x,      // (B, T, 2)
    const float* __restrict__ W1,     // (16, 32, 3)
    const float* __restrict__ b1,     // (16, 32)
    const float* __restrict__ W2,     // (16, 16, 32)
    const float* __restrict__ b2,     // (16, 16)
    const float* __restrict__ W3,     // (16, 1, 16)
    const float* __restrict__ b3,     // (16, 1)
    const float* __restrict__ logE,   // (16, 1)
    const float* __restrict__ logeta, // (16, 1)
    const float* __restrict__ imp,    // (16, 1)
    const float* __restrict__ lw,     // (4,)
    const float* __restrict__ Wf1,    // (16, 4)
    const float* __restrict__ bf1,    // (16,)
    const float* __restrict__ Wf2,    // (1, 16)
    const float* __restrict__ bf2,    // (1,)
    float* __restrict__ out)          // (4, B, T)
{
    const int b    = blockIdx.x;
    const int tid  = threadIdx.x;
    const int w    = tid >> 5;          // warp 0..7
    const int lane = tid & 31;
    const int grp  = lane >> 4;         // group within warp
    const int gl   = lane & 15;         // lane within group
    const int n    = (w << 1) | grp;    // neuron 0..15
    const unsigned rmask = grp ? 0xFFFF0000u : 0x0000FFFFu;

    // ---- per-lane weights (registers) ----
    const int i0 = gl << 1, i1 = i0 + 1;       // the two h1 rows this lane owns
    const float* W1n = W1 + n * 96;            // (32,3) row-major
    const float w1a0 = W1n[i0 * 3 + 0], w1a1 = W1n[i0 * 3 + 1], w1a2 = W1n[i0 * 3 + 2];
    const float w1b0 = W1n[i1 * 3 + 0], w1b1 = W1n[i1 * 3 + 1], w1b2 = W1n[i1 * 3 + 2];
    const float b1a  = b1[n * 32 + i0];
    const float b1b  = b1[n * 32 + i1];

    u64 w2p[16];                               // W2[n][gl][0..31] as 16 f32x2 pairs
    {
        const float4* p = (const float4*)(W2 + n * 512 + gl * 32);
#pragma unroll
        for (int q = 0; q < 8; q++) {
            float4 v = p[q];
            w2p[2 * q + 0] = pack2(v.x, v.y);
            w2p[2 * q + 1] = pack2(v.z, v.w);
        }
    }
    const float b2k  = b2[n * 16 + gl];
    const u64  b2k2  = pack2(b2k, 0.0f);
    const float w3k  = W3[n * 16 + gl];
    const float b3n  = b3[n];
    const float Ev   = expf(logE[n]);
    const float etav = expf(logeta[n]);
    const float iwv  = 1.0f / (1.0f + expf(-imp[n]));
    const float Aa   = w1a2 * iwv;             // prev-coupling, folded
    const float Ab   = w1b2 * iwv;

    // ---- shared memory ----
    // h1 staging per warp: groups at float offsets 0 and 36 (distinct bank
    // quads for the broadcast LDS.128 reads).
    __shared__ __align__(16) float sh_h1[8][80];
    __shared__ float2 sh_x[2][16];             // double-buffered x window
    __shared__ float  sh_tr[2][16][17];        // [buf][neuron][t] trace window
    __shared__ float  a_sh[16][4];             // mix consts
    __shared__ float  wf2_sh[16];
    __shared__ float  bf1_sh[16];
    __shared__ float  bf2_sh;

    const float2* x2 = (const float2*)x;

    if (tid < 16) {
        const int f = tid;
        // softmax over layer_weights + per-layer S factor, folded into Wf1
        float mx = fmaxf(fmaxf(lw[0], lw[1]), fmaxf(lw[2], lw[3]));
        float e0 = expf(lw[0] - mx), e1 = expf(lw[1] - mx);
        float e2 = expf(lw[2] - mx), e3 = expf(lw[3] - mx);
        float es = e0 + e1 + e2 + e3;
        float wl[4] = { e0 / es, e1 / es, e2 / es, e3 / es };
#pragma unroll
        for (int l = 0; l < 4; l++) {
            float s = 0.0f;
#pragma unroll
            for (int p = 0; p < 4; p++)
                s += 1.0f / (1.0f + expf(-imp[l * 4 + p]));
            float S = s / (s + 1e-8f);
            a_sh[f][l] = Wf1[f * 4 + l] * (S * wl[l]);
        }
        wf2_sh[f] = Wf2[f];
        bf1_sh[f] = bf1[f];
        if (f == 0) bf2_sh = bf2[0];
        // stage first x window
        sh_x[0][f] = x2[b * TLEN + f];
    }
    __syncthreads();

    float sumpr = 0.0f;   // carried recurrence state (= sum_k w3_k h2_k)
    float cprev = 0.0f;   // m_{u-1} + b3n (zero-init matches prev=0)
    float keep  = 0.0f;

    for (int t0 = 0; t0 < TLEN; t0 += 16) {
        const int buf = (t0 >> 4) & 1;

#pragma unroll
        for (int u = 0; u < 16; u++) {
            float2 xt = sh_x[buf][u];          // broadcast LDS.64 (off-path)
            const float strain = xt.x, rate = xt.y;

            // off-path work
            float m   = fmaf(Ev, strain, etav * rate);
            float c   = m + b3n;
            float zoa = fmaf(Aa, cprev, fmaf(w1a1, rate, fmaf(w1a0, strain, b1a)));
            float zob = fmaf(Ab, cprev, fmaf(w1b1, rate, fmaf(w1b0, strain, b1b)));

            // ---- critical path: sumpr -> z -> tanh -> h2 -> redux ----
            float ha = tanh_mufu(fmaf(Aa, sumpr, zoa));
            float hb = tanh_mufu(fmaf(Ab, sumpr, zob));

            *(float2*)&sh_h1[w][grp * 36 + i0] = make_float2(ha, hb);
            __syncwarp();   // h1 stores visible to the whole group

            const float4* hp4 = (const float4*)&sh_h1[w][grp * 36];
            float4 v0 = hp4[0], v1 = hp4[1], v2 = hp4[2], v3 = hp4[3];
            float4 v4 = hp4[4], v5 = hp4[5], v6 = hp4[6], v7 = hp4[7];
            __syncwarp();   // all lanes done reading before next iter's STS

            u64 a0 = b2k2, a1 = 0, a2 = 0, a3 = 0;
            a0 = fma2(w2p[ 0], pack2(v0.x, v0.y), a0);
            a1 = fma2(w2p[ 1], pack2(v0.z, v0.w), a1);
            a2 = fma2(w2p[ 2], pack2(v1.x, v1.y), a2);
            a3 = fma2(w2p[ 3], pack2(v1.z, v1.w), a3);
            a0 = fma2(w2p[ 4], pack2(v2.x, v2.y), a0);
            a1 = fma2(w2p[ 5], pack2(v2.z, v2.w), a1);
            a2 = fma2(w2p[ 6], pack2(v3.x, v3.y), a2);
            a3 = fma2(w2p[ 7], pack2(v3.z, v3.w), a3);
            a0 = fma2(w2p[ 8], pack2(v4.x, v4.y), a0);
            a1 = fma2(w2p[ 9], pack2(v4.z, v4.w), a1);
            a2 = fma2(w2p[10], pack2(v5.x, v5.y), a2);
            a3 = fma2(w2p[11], pack2(v5.z, v5.w), a3);
            a0 = fma2(w2p[12], pack2(v6.x, v6.y), a0);
            a1 = fma2(w2p[13], pack2(v6.z, v6.w), a1);
            a2 = fma2(w2p[14], pack2(v7.x, v7.y), a2);
            a3 = fma2(w2p[15], pack2(v7.z, v7.w), a3);

            float lo, hi;
            unpack2(add2(add2(a0, a1), add2(a2, a3)), lo, hi);
            float h2v = tanh_mufu(lo + hi);

            // fixed-point 16-lane reduction (sm_100a has no redux.f32;
            // s32 redux exists since sm_80). 2^21 scale: quantization
            // ~5e-7/step into a contractive recurrence.
            int iq = __float2int_rn((w3k * h2v) * FIXSCALE);
            int is = __reduce_add_sync(rmask, iq);
            sumpr  = (float)is * FIXISCALE;

            // output (off the recurrence chain)
            float stress = fmaf(iwv, sumpr, c * iwv);
            keep  = (gl == u) ? stress : keep;
            cprev = c;
        }

        // dump this window's traces; prefetch next x window; block sync
        sh_tr[buf][n][gl] = keep;
        if (tid < 16 && t0 + 16 < TLEN)
            sh_x[buf ^ 1][tid] = x2[b * TLEN + t0 + 16 + tid];
        __syncthreads();

        // mixing head for this window: threads 0..63 -> (t = tid&15, p = tid>>4)
        if (tid < 64) {
            const int t = tid & 15, p = tid >> 4;
            float y0 = sh_tr[buf][ 0 + p][t];
            float y1 = sh_tr[buf][ 4 + p][t];
            float y2 = sh_tr[buf][ 8 + p][t];
            float y3 = sh_tr[buf][12 + p][t];
            float o = bf2_sh;
#pragma unroll
            for (int f = 0; f < 16; f++) {
                float h = bf1_sh[f];
                h = fmaf(a_sh[f][0], y0, h);
                h = fmaf(a_sh[f][1], y1, h);
                h = fmaf(a_sh[f][2], y2, h);
                h = fmaf(a_sh[f][3], y3, h);
                o = fmaf(wf2_sh[f], fmaxf(h, 0.0f), o);
            }
            out[p * BT + b * TLEN + t0 + t] = o;
        }
        // no second barrier: sh_tr/sh_x are double-buffered, and the next
        // write to this buffer is separated by the next window's __syncthreads
    }
}

// ---------------------------------------------------------------------------
extern "C" void kernel_launch(void* const* d_in, const int* in_sizes, int n_in,
                              void* d_out, int out_size) {
    const float* x    = (const float*)d_in[0];
    const float* W1   = (const float*)d_in[1];
    const float* b1   = (const float*)d_in[2];
    const float* W2   = (const float*)d_in[3];
    const float* b2   = (const float*)d_in[4];
    const float* W3   = (const float*)d_in[5];
    const float* b3   = (const float*)d_in[6];
    const float* logE = (const float*)d_in[7];
    const float* loge = (const float*)d_in[8];
    const float* imp  = (const float*)d_in[9];
    const float* lw   = (const float*)d_in[10];
    const float* Wf1  = (const float*)d_in[11];
    const float* bf1  = (const float*)d_in[12];
    const float* Wf2  = (const float*)d_in[13];
    const float* bf2  = (const float*)d_in[14];
    float* out = (float*)d_out;

    pinn_fused_kernel<<<BATCH, 256>>>(x, W1, b1, W2, b2, W3, b3,
                                      logE, loge, imp, lw, Wf1, bf1, Wf2, bf2,
                                      out);
}

// round 9
// speedup vs baseline: 1.3423x; 1.0216x over previous
#include <cuda_runtime.h>

#define BATCH 256
#define TLEN  4096
#define BT    (BATCH * TLEN)

typedef unsigned long long u64;

__device__ __forceinline__ float tanh_mufu(float v) {
    float r;
    asm("tanh.approx.f32 %0, %1;" : "=f"(r) : "f"(v));
    return r;
}
__device__ __forceinline__ u64 pack2(float lo, float hi) {
    u64 r; asm("mov.b64 %0, {%1, %2};" : "=l"(r) : "f"(lo), "f"(hi)); return r;
}
__device__ __forceinline__ void unpack2(u64 v, float& lo, float& hi) {
    asm("mov.b64 {%0, %1}, %2;" : "=f"(lo), "=f"(hi) : "l"(v));
}
__device__ __forceinline__ u64 fma2(u64 a, u64 b, u64 c) {
    u64 d; asm("fma.rn.f32x2 %0, %1, %2, %3;" : "=l"(d) : "l"(a), "l"(b), "l"(c)); return d;
}
__device__ __forceinline__ u64 add2(u64 a, u64 b) {
    u64 d; asm("add.rn.f32x2 %0, %1, %2;" : "=l"(d) : "l"(a), "l"(b)); return d;
}

// ---------------------------------------------------------------------------
// Fully fused, max-warp kernel. Grid: 1024 blocks x 128 threads = 4096 warps
// (~7/SMSP: latency-hiding the R5/R7 designs lacked at 3.5/SMSP).
// Block bx: batch b = bx>>2, output index p = bx&3. Warp w handles neuron
// n = 4w+p — its layer is exactly w, so the block holds one neuron per
// layer and computes out[p,b,:] entirely in-block (no global scratch).
// Each chain uses the FULL 32-lane warp (R7 structure, single chain):
//   - lane l computes h1[l] (1 tanh)
//   - h2 row r=lane&15 split between lanes r / r+16 (16-wide half dots,
//     4 LDS.128 + 8 fma2), combined by one shfl_xor(16)
//   - corr: lanes 0-15 store w3*h2, all lanes re-read via broadcast
//     LDS.128 + packed add tree
// Recurrence carried as sumpr; prev enters only via z = A*sumpr + zoff,
// A = w1_2*iw (zoff computed off the critical path from cprev).
// ---------------------------------------------------------------------------
__global__ void __launch_bounds__(128, 7) pinn_fused_kernel(
    const float* __restrict__ x,      // (B, T, 2)
    const float* __restrict__ W1,     // (16, 32, 3)
    const float* __restrict__ b1,     // (16, 32)
    const float* __restrict__ W2,     // (16, 16, 32)
    const float* __restrict__ b2,     // (16, 16)
    const float* __restrict__ W3,     // (16, 1, 16)
    const float* __restrict__ b3,     // (16, 1)
    const float* __restrict__ logE,   // (16, 1)
    const float* __restrict__ logeta, // (16, 1)
    const float* __restrict__ imp,    // (16, 1)
    const float* __restrict__ lw,     // (4,)
    const float* __restrict__ Wf1,    // (16, 4)
    const float* __restrict__ bf1,    // (16,)
    const float* __restrict__ Wf2,    // (1, 16)
    const float* __restrict__ bf2,    // (1,)
    float* __restrict__ out)          // (4, B, T)
{
    const int bx   = blockIdx.x;
    const int b    = bx >> 2;
    const int p    = bx & 3;
    const int tid  = threadIdx.x;
    const int w    = tid >> 5;          // warp 0..3 == layer
    const int lane = tid & 31;
    const int r    = lane & 15;         // h2 row this lane serves
    const int half = lane >> 4;         // which 16-wide half of the dot
    const int gl   = lane & 15;
    const int n    = (w << 2) | p;      // neuron; n/4 == w (layer)

    // ---- per-lane weights (registers) ----
    const float* W1n = W1 + n * 96;     // (32,3); lane owns h1 row `lane`
    const float w10 = W1n[lane * 3 + 0];
    const float w11 = W1n[lane * 3 + 1];
    const float w12 = W1n[lane * 3 + 2];
    const float b1l = b1[n * 32 + lane];

    u64 w2h[8];                         // W2[n][r][half*16 .. +15] as 8 f32x2
    {
        const float4* q = (const float4*)(W2 + n * 512 + r * 32 + half * 16);
#pragma unroll
        for (int k = 0; k < 4; k++) {
            float4 v = q[k];
            w2h[2 * k + 0] = pack2(v.x, v.y);
            w2h[2 * k + 1] = pack2(v.z, v.w);
        }
    }
    const float b2r = b2[n * 16 + r];
    const u64 accInit = (half == 0) ? pack2(b2r, 0.0f) : pack2(0.0f, 0.0f);
    const float w3r  = W3[n * 16 + r];
    const float b3n  = b3[n];
    const float Ev   = expf(logE[n]);
    const float etav = expf(logeta[n]);
    const float iwv  = 1.0f / (1.0f + expf(-imp[n]));
    const float Al   = w12 * iwv;       // prev-coupling, folded per lane

    // ---- shared memory (tiny) ----
    __shared__ __align__(16) float sh_h1[4][32];   // per-warp h1 staging
    __shared__ __align__(16) float sh_pr[4][16];   // per-warp corr staging
    __shared__ float2 sh_x[2][16];                 // double-buffered x window
    __shared__ float  sh_tr[2][4][16];             // [buf][layer][t] traces
    __shared__ float  a_sh[16][4];                 // mixing consts
    __shared__ float  wf2_sh[16];
    __shared__ float  bf1_sh[16];
    __shared__ float  bf2_sh;

    const float2* x2 = (const float2*)x;

    if (tid < 16) {
        const int f = tid;
        float mx = fmaxf(fmaxf(lw[0], lw[1]), fmaxf(lw[2], lw[3]));
        float e0 = expf(lw[0] - mx), e1 = expf(lw[1] - mx);
        float e2 = expf(lw[2] - mx), e3 = expf(lw[3] - mx);
        float es = e0 + e1 + e2 + e3;
        float wl[4] = { e0 / es, e1 / es, e2 / es, e3 / es };
#pragma unroll
        for (int l = 0; l < 4; l++) {
            float s = 0.0f;
#pragma unroll
            for (int pp = 0; pp < 4; pp++)
                s += 1.0f / (1.0f + expf(-imp[l * 4 + pp]));
            float S = s / (s + 1e-8f);
            a_sh[f][l] = Wf1[f * 4 + l] * (S * wl[l]);
        }
        wf2_sh[f] = Wf2[f];
        bf1_sh[f] = bf1[f];
        if (f == 0) bf2_sh = bf2[0];
        sh_x[0][f] = x2[b * TLEN + f];  // stage first window
    }
    __syncthreads();

    float sumpr = 0.0f;   // carried recurrence state (= sum_k w3_k h2_k)
    float cprev = 0.0f;   // m_{u-1} + b3n (zero-init matches prev=0)
    float keep  = 0.0f;

    for (int t0 = 0; t0 < TLEN; t0 += 16) {
        const int buf = (t0 >> 4) & 1;

#pragma unroll
        for (int u = 0; u < 16; u++) {
            float2 xt = sh_x[buf][u];          // broadcast LDS.64 (off-path)
            const float strain = xt.x, rate = xt.y;

            // off-path work
            float m  = fmaf(Ev, strain, etav * rate);
            float c  = m + b3n;
            float zo = fmaf(Al, cprev,
                            fmaf(w11, rate, fmaf(w10, strain, b1l)));

            // ---- critical path: sumpr -> z -> tanh -> h2 -> reduce ----
            float h = tanh_mufu(fmaf(Al, sumpr, zo));

            sh_h1[w][lane] = h;
            __syncwarp();   // sync1: h1 stores (+ pr WAR two syncs back)

            const float4* h4 = (const float4*)&sh_h1[w][half * 16];
            float4 v0 = h4[0], v1 = h4[1], v2 = h4[2], v3 = h4[3];
            u64 a0 = accInit, a1 = 0;
            a0 = fma2(w2h[0], pack2(v0.x, v0.y), a0);
            a1 = fma2(w2h[1], pack2(v0.z, v0.w), a1);
            a0 = fma2(w2h[2], pack2(v1.x, v1.y), a0);
            a1 = fma2(w2h[3], pack2(v1.z, v1.w), a1);
            a0 = fma2(w2h[4], pack2(v2.x, v2.y), a0);
            a1 = fma2(w2h[5], pack2(v2.z, v2.w), a1);
            a0 = fma2(w2h[6], pack2(v3.x, v3.y), a0);
            a1 = fma2(w2h[7], pack2(v3.z, v3.w), a1);
            float lo, hi;
            unpack2(add2(a0, a1), lo, hi);
            float ph = lo + hi;                            // 16-wide half dot
            float full = ph + __shfl_xor_sync(0xffffffffu, ph, 16);
            float h2v = tanh_mufu(full);      // identical in lane pairs (r, r+16)

            if (half == 0) sh_pr[w][r] = w3r * h2v;
            __syncwarp();   // sync2: pr stores (+ h1 WAR)

            const float4* q4 = (const float4*)&sh_pr[w][0];
            float4 q0 = q4[0], q1 = q4[1], q2 = q4[2], q3 = q4[3];
            u64 s01 = add2(add2(pack2(q0.x, q0.y), pack2(q0.z, q0.w)),
                           add2(pack2(q1.x, q1.y), pack2(q1.z, q1.w)));
            u64 s23 = add2(add2(pack2(q2.x, q2.y), pack2(q2.z, q2.w)),
                           add2(pack2(q3.x, q3.y), pack2(q3.z, q3.w)));
            float rlo, rhi;
            unpack2(add2(s01, s23), rlo, rhi);
            sumpr = rlo + rhi;

            // output (off the recurrence chain); warp-uniform
            float stress = fmaf(iwv, sumpr, c * iwv);
            keep  = (gl == u) ? stress : keep;
            cprev = c;
        }

        // dump window traces; prefetch next x (warp 3 upper half); barrier
        if (half == 0) sh_tr[buf][w][gl] = keep;
        if (w == 3 && half == 1 && t0 + 16 < TLEN)
            sh_x[buf ^ 1][gl] = x2[b * TLEN + t0 + 16 + gl];
        __syncthreads();

        // mixing head for this window: threads 0..15, one t each
        if (tid < 16) {
            float y0 = sh_tr[buf][0][tid];
            float y1 = sh_tr[buf][1][tid];
            float y2 = sh_tr[buf][2][tid];
            float y3 = sh_tr[buf][3][tid];
            float o = bf2_sh;
#pragma unroll
            for (int f = 0; f < 16; f++) {
                float hm = bf1_sh[f];
                hm = fmaf(a_sh[f][0], y0, hm);
                hm = fmaf(a_sh[f][1], y1, hm);
                hm = fmaf(a_sh[f][2], y2, hm);
                hm = fmaf(a_sh[f][3], y3, hm);
                o = fmaf(wf2_sh[f], fmaxf(hm, 0.0f), o);
            }
            out[p * BT + b * TLEN + t0 + tid] = o;
        }
        // sh_tr/sh_x double-buffered: next overwrite of this buffer is
        // separated by the NEXT window's __syncthreads.
    }
}

// ---------------------------------------------------------------------------
extern "C" void kernel_launch(void* const* d_in, const int* in_sizes, int n_in,
                              void* d_out, int out_size) {
    const float* x    = (const float*)d_in[0];
    const float* W1   = (const float*)d_in[1];
    const float* b1   = (const float*)d_in[2];
    const float* W2   = (const float*)d_in[3];
    const float* b2   = (const float*)d_in[4];
    const float* W3   = (const float*)d_in[5];
    const float* b3   = (const float*)d_in[6];
    const float* logE = (const float*)d_in[7];
    const float* loge = (const float*)d_in[8];
    const float* imp  = (const float*)d_in[9];
    const float* lw   = (const float*)d_in[10];
    const float* Wf1  = (const float*)d_in[11];
    const float* bf1  = (const float*)d_in[12];
    const float* Wf2  = (const float*)d_in[13];
    const float* bf2  = (const float*)d_in[14];
    float* out = (float*)d_out;

    pinn_fused_kernel<<<BATCH * 4, 128>>>(x, W1, b1, W2, b2, W3, b3,
                                          logE, loge, imp, lw, Wf1, bf1,
                                          Wf2, bf2, out);
}

// round 10
// speedup vs baseline: 1.5460x; 1.1517x over previous
#include <cuda_runtime.h>

#define BATCH 256
#define TLEN  4096
#define BT    (BATCH * TLEN)

typedef unsigned long long u64;

__device__ __forceinline__ float tanh_mufu(float v) {
    float r;
    asm("tanh.approx.f32 %0, %1;" : "=f"(r) : "f"(v));
    return r;
}
__device__ __forceinline__ u64 pack2(float lo, float hi) {
    u64 r; asm("mov.b64 %0, {%1, %2};" : "=l"(r) : "f"(lo), "f"(hi)); return r;
}
__device__ __forceinline__ void unpack2(u64 v, float& lo, float& hi) {
    asm("mov.b64 {%0, %1}, %2;" : "=f"(lo), "=f"(hi) : "l"(v));
}
__device__ __forceinline__ u64 fma2(u64 a, u64 b, u64 c) {
    u64 d; asm("fma.rn.f32x2 %0, %1, %2, %3;" : "=l"(d) : "l"(a), "l"(b), "l"(c)); return d;
}
__device__ __forceinline__ u64 add2(u64 a, u64 b) {
    u64 d; asm("add.rn.f32x2 %0, %1, %2;" : "=l"(d) : "l"(a), "l"(b)); return d;
}

// ---------------------------------------------------------------------------
// Fully fused kernel, v2: R9 structure (1024 blocks x 128 thr = 4096 warps,
// block = (batch, p-output), warp = one neuron = one layer, full in-block
// mixing head) with the SHARED-PIPE bottleneck (ncu: L1 = 88.9%) attacked:
//   - the corr reduction (was STS + syncwarp + 4x LDS.128 + tree) is now a
//     4-stage shfl_xor butterfly — lanes r and r+16 hold bitwise-identical
//     h2 values after the half-combine shfl, so the butterfly over masks
//     1/2/4/8 yields the exact 16-row sum in every lane. Zero smem, zero
//     syncs on that segment.
//   - x window reads: one broadcast LDS.128 per TWO steps (float4 = 2 ts).
// Shared-pipe ops/warp-step: ~11 -> ~6.
// Recurrence carried as sumpr; prev enters only via z = A*sumpr + zoff.
// ---------------------------------------------------------------------------
__global__ void __launch_bounds__(128, 7) pinn_fused_kernel(
    const float* __restrict__ x,      // (B, T, 2)
    const float* __restrict__ W1,     // (16, 32, 3)
    const float* __restrict__ b1,     // (16, 32)
    const float* __restrict__ W2,     // (16, 16, 32)
    const float* __restrict__ b2,     // (16, 16)
    const float* __restrict__ W3,     // (16, 1, 16)
    const float* __restrict__ b3,     // (16, 1)
    const float* __restrict__ logE,   // (16, 1)
    const float* __restrict__ logeta, // (16, 1)
    const float* __restrict__ imp,    // (16, 1)
    const float* __restrict__ lw,     // (4,)
    const float* __restrict__ Wf1,    // (16, 4)
    const float* __restrict__ bf1,    // (16,)
    const float* __restrict__ Wf2,    // (1, 16)
    const float* __restrict__ bf2,    // (1,)
    float* __restrict__ out)          // (4, B, T)
{
    const int bx   = blockIdx.x;
    const int b    = bx >> 2;
    const int p    = bx & 3;
    const int tid  = threadIdx.x;
    const int w    = tid >> 5;          // warp 0..3 == layer
    const int lane = tid & 31;
    const int r    = lane & 15;         // h2 row this lane serves
    const int half = lane >> 4;         // which 16-wide half of the dot
    const int gl   = lane & 15;
    const int n    = (w << 2) | p;      // neuron; n/4 == w (layer)

    // ---- per-lane weights (registers) ----
    const float* W1n = W1 + n * 96;     // (32,3); lane owns h1 row `lane`
    const float w10 = W1n[lane * 3 + 0];
    const float w11 = W1n[lane * 3 + 1];
    const float w12 = W1n[lane * 3 + 2];
    const float b1l = b1[n * 32 + lane];

    u64 w2h[8];                         // W2[n][r][half*16 .. +15] as 8 f32x2
    {
        const float4* q = (const float4*)(W2 + n * 512 + r * 32 + half * 16);
#pragma unroll
        for (int k = 0; k < 4; k++) {
            float4 v = q[k];
            w2h[2 * k + 0] = pack2(v.x, v.y);
            w2h[2 * k + 1] = pack2(v.z, v.w);
        }
    }
    const float b2r = b2[n * 16 + r];
    const u64 accInit = (half == 0) ? pack2(b2r, 0.0f) : pack2(0.0f, 0.0f);
    const float w3r  = W3[n * 16 + r];
    const float b3n  = b3[n];
    const float Ev   = expf(logE[n]);
    const float etav = expf(logeta[n]);
    const float iwv  = 1.0f / (1.0f + expf(-imp[n]));
    const float Al   = w12 * iwv;       // prev-coupling, folded per lane

    // ---- shared memory (tiny) ----
    __shared__ __align__(16) float  sh_h1[4][32];  // per-warp h1 staging
    __shared__ __align__(16) float2 sh_x[2][16];   // double-buffered x window
    __shared__ float  sh_tr[2][4][16];             // [buf][layer][t] traces
    __shared__ float  a_sh[16][4];                 // mixing consts
    __shared__ float  wf2_sh[16];
    __shared__ float  bf1_sh[16];
    __shared__ float  bf2_sh;

    const float2* x2 = (const float2*)x;

    if (tid < 16) {
        const int f = tid;
        float mx = fmaxf(fmaxf(lw[0], lw[1]), fmaxf(lw[2], lw[3]));
        float e0 = expf(lw[0] - mx), e1 = expf(lw[1] - mx);
        float e2 = expf(lw[2] - mx), e3 = expf(lw[3] - mx);
        float es = e0 + e1 + e2 + e3;
        float wl[4] = { e0 / es, e1 / es, e2 / es, e3 / es };
#pragma unroll
        for (int l = 0; l < 4; l++) {
            float s = 0.0f;
#pragma unroll
            for (int pp = 0; pp < 4; pp++)
                s += 1.0f / (1.0f + expf(-imp[l * 4 + pp]));
            float S = s / (s + 1e-8f);
            a_sh[f][l] = Wf1[f * 4 + l] * (S * wl[l]);
        }
        wf2_sh[f] = Wf2[f];
        bf1_sh[f] = bf1[f];
        if (f == 0) bf2_sh = bf2[0];
        sh_x[0][f] = x2[b * TLEN + f];  // stage first window
    }
    __syncthreads();

    float sumpr = 0.0f;   // carried recurrence state (= sum_k w3_k h2_k)
    float cprev = 0.0f;   // m_{u-1} + b3n (zero-init matches prev=0)
    float keep  = 0.0f;

    for (int t0 = 0; t0 < TLEN; t0 += 16) {
        const int buf = (t0 >> 4) & 1;
        const float4* xw4 = (const float4*)&sh_x[buf][0];

#pragma unroll
        for (int v2i = 0; v2i < 8; v2i++) {         // 2 timesteps per iter
            float4 xx = xw4[v2i];                    // broadcast LDS.128
#pragma unroll
            for (int s = 0; s < 2; s++) {
                const int   u      = 2 * v2i + s;
                const float strain = s ? xx.z : xx.x;
                const float rate   = s ? xx.w : xx.y;

                // off-path work
                float m  = fmaf(Ev, strain, etav * rate);
                float c  = m + b3n;
                float zo = fmaf(Al, cprev,
                                fmaf(w11, rate, fmaf(w10, strain, b1l)));

                // ---- critical path: sumpr -> z -> tanh -> h2 -> butterfly ----
                float h = tanh_mufu(fmaf(Al, sumpr, zo));

                sh_h1[w][lane] = h;
                __syncwarp();   // h1 stores visible (also WAR for prev read)

                const float4* h4 = (const float4*)&sh_h1[w][half * 16];
                float4 v0 = h4[0], v1 = h4[1], v2 = h4[2], v3 = h4[3];
                u64 a0 = accInit, a1 = 0;
                a0 = fma2(w2h[0], pack2(v0.x, v0.y), a0);
                a1 = fma2(w2h[1], pack2(v0.z, v0.w), a1);
                a0 = fma2(w2h[2], pack2(v1.x, v1.y), a0);
                a1 = fma2(w2h[3], pack2(v1.z, v1.w), a1);
                a0 = fma2(w2h[4], pack2(v2.x, v2.y), a0);
                a1 = fma2(w2h[5], pack2(v2.z, v2.w), a1);
                a0 = fma2(w2h[6], pack2(v3.x, v3.y), a0);
                a1 = fma2(w2h[7], pack2(v3.z, v3.w), a1);
                float lo, hi;
                unpack2(add2(a0, a1), lo, hi);
                float ph = lo + hi;                  // 16-wide half dot
                // combine halves: lanes r and r+16 now bitwise-identical
                float full = ph + __shfl_xor_sync(0xffffffffu, ph, 16);
                float pr = w3r * tanh_mufu(full);

                // 16-row sum via butterfly (halves duplicated -> masks 1..8)
                pr += __shfl_xor_sync(0xffffffffu, pr, 1);
                pr += __shfl_xor_sync(0xffffffffu, pr, 2);
                pr += __shfl_xor_sync(0xffffffffu, pr, 4);
                pr += __shfl_xor_sync(0xffffffffu, pr, 8);
                sumpr = pr;

                // output (off the recurrence chain)
                float stress = fmaf(iwv, sumpr, c * iwv);
                keep  = (gl == u) ? stress : keep;
                cprev = c;
            }
        }

        // dump window traces; prefetch next x (warp 3 upper half); barrier
        if (half == 0) sh_tr[buf][w][gl] = keep;
        if (w == 3 && half == 1 && t0 + 16 < TLEN)
            sh_x[buf ^ 1][gl] = x2[b * TLEN + t0 + 16 + gl];
        __syncthreads();

        // mixing head for this window: threads 0..15, one t each
        if (tid < 16) {
            float y0 = sh_tr[buf][0][tid];
            float y1 = sh_tr[buf][1][tid];
            float y2 = sh_tr[buf][2][tid];
            float y3 = sh_tr[buf][3][tid];
            float o = bf2_sh;
#pragma unroll
            for (int f = 0; f < 16; f++) {
                float hm = bf1_sh[f];
                hm = fmaf(a_sh[f][0], y0, hm);
                hm = fmaf(a_sh[f][1], y1, hm);
                hm = fmaf(a_sh[f][2], y2, hm);
                hm = fmaf(a_sh[f][3], y3, hm);
                o = fmaf(wf2_sh[f], fmaxf(hm, 0.0f), o);
            }
            out[p * BT + b * TLEN + t0 + tid] = o;
        }
        // sh_tr/sh_x double-buffered: next overwrite of this buffer is
        // separated by the NEXT window's __syncthreads.
    }
}

// ---------------------------------------------------------------------------
extern "C" void kernel_launch(void* const* d_in, const int* in_sizes, int n_in,
                              void* d_out, int out_size) {
    const float* x    = (const float*)d_in[0];
    const float* W1   = (const float*)d_in[1];
    const float* b1   = (const float*)d_in[2];
    const float* W2   = (const float*)d_in[3];
    const float* b2   = (const float*)d_in[4];
    const float* W3   = (const float*)d_in[5];
    const float* b3   = (const float*)d_in[6];
    const float* logE = (const float*)d_in[7];
    const float* loge = (const float*)d_in[8];
    const float* imp  = (const float*)d_in[9];
    const float* lw   = (const float*)d_in[10];
    const float* Wf1  = (const float*)d_in[11];
    const float* bf1  = (const float*)d_in[12];
    const float* Wf2  = (const float*)d_in[13];
    const float* bf2  = (const float*)d_in[14];
    float* out = (float*)d_out;

    pinn_fused_kernel<<<BATCH * 4, 128>>>(x, W1, b1, W2, b2, W3, b3,
                                          logE, loge, imp, lw, Wf1, bf1,
                                          Wf2, bf2, out);
}

// round 11
// speedup vs baseline: 1.6889x; 1.0924x over previous
#include <cuda_runtime.h>

#define BATCH 256
#define TLEN  4096
#define BT    (BATCH * TLEN)

typedef unsigned long long u64;

#define FIXSCALE   2097152.0f          // 2^21
#define FIXISCALE  (1.0f / 2097152.0f)

__device__ __forceinline__ float tanh_mufu(float v) {
    float r;
    asm("tanh.approx.f32 %0, %1;" : "=f"(r) : "f"(v));
    return r;
}
__device__ __forceinline__ u64 pack2(float lo, float hi) {
    u64 r; asm("mov.b64 %0, {%1, %2};" : "=l"(r) : "f"(lo), "f"(hi)); return r;
}
__device__ __forceinline__ void unpack2(u64 v, float& lo, float& hi) {
    asm("mov.b64 {%0, %1}, %2;" : "=f"(lo), "=f"(hi) : "l"(v));
}
__device__ __forceinline__ u64 fma2(u64 a, u64 b, u64 c) {
    u64 d; asm("fma.rn.f32x2 %0, %1, %2, %3;" : "=l"(d) : "l"(a), "l"(b), "l"(c)); return d;
}
__device__ __forceinline__ u64 add2(u64 a, u64 b) {
    u64 d; asm("add.rn.f32x2 %0, %1, %2;" : "=l"(d) : "l"(a), "l"(b)); return d;
}

// ---------------------------------------------------------------------------
// Fully fused kernel, v3: R10 structure (1024 blocks x 128 thr = 4096 warps,
// block = (batch, p-output), warp = one neuron = one layer, in-block mixing
// head) with the 4-stage shfl butterfly (≈120 serial cyc + 4 MIO ops) in the
// corr reduction replaced by ONE s32 __reduce_add_sync (sm_80+; only the
// .f32 form needs sm_103):
//   - after the mask-16 half-combine, lanes r and r+16 hold identical h2;
//     a FULL-warp integer redux therefore returns exactly 2x the 16-row
//     sum — folding 0.5 into the pre-scaled w3 makes the result exact.
//   - fixed point at 2^21 (R8-validated: quantization ~5e-7, contractive
//     recurrence, rel_err stays ~6.5e-7).
// Per-step MIO ops ~10.5 -> ~6.5 (relieves the measured 81% L1 pipe);
// serial chain ~305 -> ~260 cyc.
// Recurrence carried as sumpr; prev enters only via z = A*sumpr + zoff.
// ---------------------------------------------------------------------------
__global__ void __launch_bounds__(128, 7) pinn_fused_kernel(
    const float* __restrict__ x,      // (B, T, 2)
    const float* __restrict__ W1,     // (16, 32, 3)
    const float* __restrict__ b1,     // (16, 32)
    const float* __restrict__ W2,     // (16, 16, 32)
    const float* __restrict__ b2,     // (16, 16)
    const float* __restrict__ W3,     // (16, 1, 16)
    const float* __restrict__ b3,     // (16, 1)
    const float* __restrict__ logE,   // (16, 1)
    const float* __restrict__ logeta, // (16, 1)
    const float* __restrict__ imp,    // (16, 1)
    const float* __restrict__ lw,     // (4,)
    const float* __restrict__ Wf1,    // (16, 4)
    const float* __restrict__ bf1,    // (16,)
    const float* __restrict__ Wf2,    // (1, 16)
    const float* __restrict__ bf2,    // (1,)
    float* __restrict__ out)          // (4, B, T)
{
    const int bx   = blockIdx.x;
    const int b    = bx >> 2;
    const int p    = bx & 3;
    const int tid  = threadIdx.x;
    const int w    = tid >> 5;          // warp 0..3 == layer
    const int lane = tid & 31;
    const int r    = lane & 15;         // h2 row this lane serves
    const int half = lane >> 4;         // which 16-wide half of the dot
    const int gl   = lane & 15;
    const int n    = (w << 2) | p;      // neuron; n/4 == w (layer)

    // ---- per-lane weights (registers) ----
    const float* W1n = W1 + n * 96;     // (32,3); lane owns h1 row `lane`
    const float w10 = W1n[lane * 3 + 0];
    const float w11 = W1n[lane * 3 + 1];
    const float w12 = W1n[lane * 3 + 2];
    const float b1l = b1[n * 32 + lane];

    u64 w2h[8];                         // W2[n][r][half*16 .. +15] as 8 f32x2
    {
        const float4* q = (const float4*)(W2 + n * 512 + r * 32 + half * 16);
#pragma unroll
        for (int k = 0; k < 4; k++) {
            float4 v = q[k];
            w2h[2 * k + 0] = pack2(v.x, v.y);
            w2h[2 * k + 1] = pack2(v.z, v.w);
        }
    }
    const float b2r = b2[n * 16 + r];
    const u64 accInit = (half == 0) ? pack2(b2r, 0.0f) : pack2(0.0f, 0.0f);
    // 0.5 (full-warp redux double-counts the duplicated halves) and the
    // fixed-point scale folded into w3:
    const float w3s  = 0.5f * FIXSCALE * W3[n * 16 + r];
    const float b3n  = b3[n];
    const float Ev   = expf(logE[n]);
    const float etav = expf(logeta[n]);
    const float iwv  = 1.0f / (1.0f + expf(-imp[n]));
    const float Al   = w12 * iwv;       // prev-coupling, folded per lane

    // ---- shared memory (tiny) ----
    __shared__ __align__(16) float  sh_h1[4][32];  // per-warp h1 staging
    __shared__ __align__(16) float2 sh_x[2][16];   // double-buffered x window
    __shared__ float  sh_tr[2][4][16];             // [buf][layer][t] traces
    __shared__ float  a_sh[16][4];                 // mixing consts
    __shared__ float  wf2_sh[16];
    __shared__ float  bf1_sh[16];
    __shared__ float  bf2_sh;

    const float2* x2 = (const float2*)x;

    if (tid < 16) {
        const int f = tid;
        float mx = fmaxf(fmaxf(lw[0], lw[1]), fmaxf(lw[2], lw[3]));
        float e0 = expf(lw[0] - mx), e1 = expf(lw[1] - mx);
        float e2 = expf(lw[2] - mx), e3 = expf(lw[3] - mx);
        float es = e0 + e1 + e2 + e3;
        float wl[4] = { e0 / es, e1 / es, e2 / es, e3 / es };
#pragma unroll
        for (int l = 0; l < 4; l++) {
            float s = 0.0f;
#pragma unroll
            for (int pp = 0; pp < 4; pp++)
                s += 1.0f / (1.0f + expf(-imp[l * 4 + pp]));
            float S = s / (s + 1e-8f);
            a_sh[f][l] = Wf1[f * 4 + l] * (S * wl[l]);
        }
        wf2_sh[f] = Wf2[f];
        bf1_sh[f] = bf1[f];
        if (f == 0) bf2_sh = bf2[0];
        sh_x[0][f] = x2[b * TLEN + f];  // stage first window
    }
    __syncthreads();

    float sumpr = 0.0f;   // carried recurrence state (= sum_k w3_k h2_k)
    float cprev = 0.0f;   // m_{u-1} + b3n (zero-init matches prev=0)
    float keep  = 0.0f;

    for (int t0 = 0; t0 < TLEN; t0 += 16) {
        const int buf = (t0 >> 4) & 1;
        const float4* xw4 = (const float4*)&sh_x[buf][0];

#pragma unroll
        for (int v2i = 0; v2i < 8; v2i++) {         // 2 timesteps per iter
            float4 xx = xw4[v2i];                    // broadcast LDS.128
#pragma unroll
            for (int s = 0; s < 2; s++) {
                const int   u      = 2 * v2i + s;
                const float strain = s ? xx.z : xx.x;
                const float rate   = s ? xx.w : xx.y;

                // off-path work
                float m  = fmaf(Ev, strain, etav * rate);
                float c  = m + b3n;
                float zo = fmaf(Al, cprev,
                                fmaf(w11, rate, fmaf(w10, strain, b1l)));

                // ---- critical path: sumpr -> z -> tanh -> h2 -> redux ----
                float h = tanh_mufu(fmaf(Al, sumpr, zo));

                sh_h1[w][lane] = h;
                __syncwarp();   // h1 stores visible (also WAR for prev read)

                const float4* h4 = (const float4*)&sh_h1[w][half * 16];
                float4 v0 = h4[0], v1 = h4[1], v2 = h4[2], v3 = h4[3];
                u64 a0 = accInit, a1 = 0;
                a0 = fma2(w2h[0], pack2(v0.x, v0.y), a0);
                a1 = fma2(w2h[1], pack2(v0.z, v0.w), a1);
                a0 = fma2(w2h[2], pack2(v1.x, v1.y), a0);
                a1 = fma2(w2h[3], pack2(v1.z, v1.w), a1);
                a0 = fma2(w2h[4], pack2(v2.x, v2.y), a0);
                a1 = fma2(w2h[5], pack2(v2.z, v2.w), a1);
                a0 = fma2(w2h[6], pack2(v3.x, v3.y), a0);
                a1 = fma2(w2h[7], pack2(v3.z, v3.w), a1);
                float lo, hi;
                unpack2(add2(a0, a1), lo, hi);
                float ph = lo + hi;                  // 16-wide half dot
                // combine halves: lanes r and r+16 now bitwise-identical
                float full = ph + __shfl_xor_sync(0xffffffffu, ph, 16);
                float h2v = tanh_mufu(full);

                // 16-row sum via ONE full-warp s32 redux (duplicates folded
                // into the 0.5 in w3s; fixed point 2^21)
                int iq = __float2int_rn(w3s * h2v);
                int is = __reduce_add_sync(0xffffffffu, iq);
                sumpr  = (float)is * FIXISCALE;

                // output (off the recurrence chain)
                float stress = fmaf(iwv, sumpr, c * iwv);
                keep  = (gl == u) ? stress : keep;
                cprev = c;
            }
        }

        // dump window traces; prefetch next x (warp 3 upper half); barrier
        if (half == 0) sh_tr[buf][w][gl] = keep;
        if (w == 3 && half == 1 && t0 + 16 < TLEN)
            sh_x[buf ^ 1][gl] = x2[b * TLEN + t0 + 16 + gl];
        __syncthreads();

        // mixing head for this window: threads 0..15, one t each
        if (tid < 16) {
            float y0 = sh_tr[buf][0][tid];
            float y1 = sh_tr[buf][1][tid];
            float y2 = sh_tr[buf][2][tid];
            float y3 = sh_tr[buf][3][tid];
            float o = bf2_sh;
#pragma unroll
            for (int f = 0; f < 16; f++) {
                float hm = bf1_sh[f];
                hm = fmaf(a_sh[f][0], y0, hm);
                hm = fmaf(a_sh[f][1], y1, hm);
                hm = fmaf(a_sh[f][2], y2, hm);
                hm = fmaf(a_sh[f][3], y3, hm);
                o = fmaf(wf2_sh[f], fmaxf(hm, 0.0f), o);
            }
            out[p * BT + b * TLEN + t0 + tid] = o;
        }
        // sh_tr/sh_x double-buffered: next overwrite of this buffer is
        // separated by the NEXT window's __syncthreads.
    }
}

// ---------------------------------------------------------------------------
extern "C" void kernel_launch(void* const* d_in, const int* in_sizes, int n_in,
                              void* d_out, int out_size) {
    const float* x    = (const float*)d_in[0];
    const float* W1   = (const float*)d_in[1];
    const float* b1   = (const float*)d_in[2];
    const float* W2   = (const float*)d_in[3];
    const float* b2   = (const float*)d_in[4];
    const float* W3   = (const float*)d_in[5];
    const float* b3   = (const float*)d_in[6];
    const float* logE = (const float*)d_in[7];
    const float* loge = (const float*)d_in[8];
    const float* imp  = (const float*)d_in[9];
    const float* lw   = (const float*)d_in[10];
    const float* Wf1  = (const float*)d_in[11];
    const float* bf1  = (const float*)d_in[12];
    const float* Wf2  = (const float*)d_in[13];
    const float* bf2  = (const float*)d_in[14];
    float* out = (float*)d_out;

    pinn_fused_kernel<<<BATCH * 4, 128>>>(x, W1, b1, W2, b2, W3, b3,
                                          logE, loge, imp, lw, Wf1, bf1,
                                          Wf2, bf2, out);
}

// round 12
// speedup vs baseline: 1.8428x; 1.0911x over previous
#include <cuda_runtime.h>

#define BATCH 256
#define TLEN  4096
#define BT    (BATCH * TLEN)

typedef unsigned long long u64;

#define FIXSCALE  262144.0f            // 2^18
#define MAGICF    12582912.0f          // 1.5 * 2^23
// 32 * 0x4B400000 mod 2^32 = 0x68000000 ; 0x68000000 - 0x4B400000 = 0x1CC00000
#define BIAS_SUB  0x1CC00000

__device__ __forceinline__ float tanh_mufu(float v) {
    float r;
    asm("tanh.approx.f32 %0, %1;" : "=f"(r) : "f"(v));
    return r;
}
__device__ __forceinline__ u64 pack2(float lo, float hi) {
    u64 r; asm("mov.b64 %0, {%1, %2};" : "=l"(r) : "f"(lo), "f"(hi)); return r;
}
__device__ __forceinline__ void unpack2(u64 v, float& lo, float& hi) {
    asm("mov.b64 {%0, %1}, %2;" : "=f"(lo), "=f"(hi) : "l"(v));
}
__device__ __forceinline__ u64 fma2(u64 a, u64 b, u64 c) {
    u64 d; asm("fma.rn.f32x2 %0, %1, %2, %3;" : "=l"(d) : "l"(a), "l"(b), "l"(c)); return d;
}
__device__ __forceinline__ u64 add2(u64 a, u64 b) {
    u64 d; asm("add.rn.f32x2 %0, %1, %2;" : "=l"(d) : "l"(a), "l"(b)); return d;
}

// ---------------------------------------------------------------------------
// Fully fused kernel, v4: R11 winner (1024 blocks x 128 thr, block =
// (batch, p-output), warp = one neuron = one layer, in-block mixing head)
// with the XU pipe (2 tanh + F2I + I2F = 224 cyc/SMSP demand) relieved:
//   - fixed-point conversion via the 1.5*2^23 magic-bias trick: the
//     float->int and int->float hops become FMA/IADD/FADD (fma/alu pipes),
//     and the redux sums the per-lane biases modularly (32*bias mod 2^32
//     re-biased with one IADD). FIXSCALE = 2^18 keeps |sum| < 2^22 so the
//     reverse magic stays exact. The w3 multiply and both scale factors
//     fold into existing constants (Al18, iw18, w3s).
//   - window 16 -> 32 steps: lane u keeps step u; barrier + mix + staging
//     amortize over 2x steps; warp 0 mixes 32 t's in one pass.
//   - b3n folded into b1l2/b3iw; carried state is mprev (init -b3n).
// Recurrence carried as the scaled redux sum; prev enters only via
// z = Al18*sum_f + zoff.
// ---------------------------------------------------------------------------
__global__ void __launch_bounds__(128, 7) pinn_fused_kernel(
    const float* __restrict__ x,      // (B, T, 2)
    const float* __restrict__ W1,     // (16, 32, 3)
    const float* __restrict__ b1,     // (16, 32)
    const float* __restrict__ W2,     // (16, 16, 32)
    const float* __restrict__ b2,     // (16, 16)
    const float* __restrict__ W3,     // (16, 1, 16)
    const float* __restrict__ b3,     // (16, 1)
    const float* __restrict__ logE,   // (16, 1)
    const float* __restrict__ logeta, // (16, 1)
    const float* __restrict__ imp,    // (16, 1)
    const float* __restrict__ lw,     // (4,)
    const float* __restrict__ Wf1,    // (16, 4)
    const float* __restrict__ bf1,    // (16,)
    const float* __restrict__ Wf2,    // (1, 16)
    const float* __restrict__ bf2,    // (1,)
    float* __restrict__ out)          // (4, B, T)
{
    const int bx   = blockIdx.x;
    const int b    = bx >> 2;
    const int p    = bx & 3;
    const int tid  = threadIdx.x;
    const int w    = tid >> 5;          // warp 0..3 == layer
    const int lane = tid & 31;
    const int r    = lane & 15;         // h2 row this lane serves
    const int half = lane >> 4;         // which 16-wide half of the dot
    const int n    = (w << 2) | p;      // neuron; n/4 == w (layer)

    // ---- per-lane weights (registers) ----
    const float* W1n = W1 + n * 96;     // (32,3); lane owns h1 row `lane`
    const float w10 = W1n[lane * 3 + 0];
    const float w11 = W1n[lane * 3 + 1];
    const float w12 = W1n[lane * 3 + 2];

    u64 w2h[8];                         // W2[n][r][half*16 .. +15] as 8 f32x2
    {
        const float4* q = (const float4*)(W2 + n * 512 + r * 32 + half * 16);
#pragma unroll
        for (int k = 0; k < 4; k++) {
            float4 v = q[k];
            w2h[2 * k + 0] = pack2(v.x, v.y);
            w2h[2 * k + 1] = pack2(v.z, v.w);
        }
    }
    const float b2r = b2[n * 16 + r];
    const u64 accInit = (half == 0) ? pack2(b2r, 0.0f) : pack2(0.0f, 0.0f);
    // 0.5 (full-warp redux double-counts halves) * 2^18 folded into w3:
    const float w3s  = 0.5f * FIXSCALE * W3[n * 16 + r];
    const float b3n  = b3[n];
    const float Ev   = expf(logE[n]);
    const float etav = expf(logeta[n]);
    const float iwv  = 1.0f / (1.0f + expf(-imp[n]));
    const float Al   = w12 * iwv;              // prev-coupling, folded
    const float Al18 = Al * (1.0f / FIXSCALE); // applied to the scaled sum
    const float iw18 = iwv * (1.0f / FIXSCALE);
    const float b3iw = b3n * iwv;
    const float b1l2 = b1[n * 32 + lane] + Al * b3n;  // b3n folded into bias

    // ---- shared memory (tiny) ----
    __shared__ __align__(16) float  sh_h1[4][32];  // per-warp h1 staging
    __shared__ __align__(16) float2 sh_x[2][32];   // double-buffered x window
    __shared__ float  sh_tr[2][4][32];             // [buf][layer][t] traces
    __shared__ float  a_sh[16][4];                 // mixing consts
    __shared__ float  wf2_sh[16];
    __shared__ float  bf1_sh[16];
    __shared__ float  bf2_sh;

    const float2* x2 = (const float2*)x;

    if (tid < 16) {
        const int f = tid;
        float mx = fmaxf(fmaxf(lw[0], lw[1]), fmaxf(lw[2], lw[3]));
        float e0 = expf(lw[0] - mx), e1 = expf(lw[1] - mx);
        float e2 = expf(lw[2] - mx), e3 = expf(lw[3] - mx);
        float es = e0 + e1 + e2 + e3;
        float wl[4] = { e0 / es, e1 / es, e2 / es, e3 / es };
#pragma unroll
        for (int l = 0; l < 4; l++) {
            float s = 0.0f;
#pragma unroll
            for (int pp = 0; pp < 4; pp++)
                s += 1.0f / (1.0f + expf(-imp[l * 4 + pp]));
            float S = s / (s + 1e-8f);
            a_sh[f][l] = Wf1[f * 4 + l] * (S * wl[l]);
        }
        wf2_sh[f] = Wf2[f];
        bf1_sh[f] = bf1[f];
        if (f == 0) bf2_sh = bf2[0];
    }
    if (tid < 32) sh_x[0][tid] = x2[b * TLEN + tid];   // stage first window
    __syncthreads();

    float sumf  = 0.0f;    // carried scaled recurrence sum (2^18 units)
    float mprev = -b3n;    // carried maxwell term; -b3n cancels folded bias at u=0
    float keep  = 0.0f;

    for (int t0 = 0; t0 < TLEN; t0 += 32) {
        const int buf = (t0 >> 5) & 1;
        const float4* xw4 = (const float4*)&sh_x[buf][0];

#pragma unroll
        for (int v2i = 0; v2i < 16; v2i++) {        // 2 timesteps per iter
            float4 xx = xw4[v2i];                    // broadcast LDS.128
#pragma unroll
            for (int s = 0; s < 2; s++) {
                const int   u      = 2 * v2i + s;
                const float strain = s ? xx.z : xx.x;
                const float rate   = s ? xx.w : xx.y;

                // off-path work (b3n pre-folded into b1l2)
                float m  = fmaf(Ev, strain, etav * rate);
                float zo = fmaf(Al, mprev,
                                fmaf(w11, rate, fmaf(w10, strain, b1l2)));

                // ---- critical path: sumf -> z -> tanh -> h2 -> redux ----
                float h = tanh_mufu(fmaf(Al18, sumf, zo));

                sh_h1[w][lane] = h;
                __syncwarp();   // h1 stores visible (also WAR for prev read)

                const float4* h4 = (const float4*)&sh_h1[w][half * 16];
                float4 v0 = h4[0], v1 = h4[1], v2 = h4[2], v3 = h4[3];
                u64 a0 = accInit, a1 = 0;
                a0 = fma2(w2h[0], pack2(v0.x, v0.y), a0);
                a1 = fma2(w2h[1], pack2(v0.z, v0.w), a1);
                a0 = fma2(w2h[2], pack2(v1.x, v1.y), a0);
                a1 = fma2(w2h[3], pack2(v1.z, v1.w), a1);
                a0 = fma2(w2h[4], pack2(v2.x, v2.y), a0);
                a1 = fma2(w2h[5], pack2(v2.z, v2.w), a1);
                a0 = fma2(w2h[6], pack2(v3.x, v3.y), a0);
                a1 = fma2(w2h[7], pack2(v3.z, v3.w), a1);
                float lo, hi;
                unpack2(add2(a0, a1), lo, hi);
                float ph = lo + hi;                  // 16-wide half dot
                // combine halves: lanes r and r+16 now bitwise-identical
                float full = ph + __shfl_xor_sync(0xffffffffu, ph, 16);
                float h2v = tanh_mufu(full);

                // magic-bias fixed point: the fma result's bit pattern IS
                // bias + round(w3s*h2v); redux sums biases modularly.
                int ib = __float_as_int(fmaf(w3s, h2v, MAGICF));
                int is = __reduce_add_sync(0xffffffffu, ib);
                sumf   = __int_as_float(is - BIAS_SUB) - MAGICF;  // = sum(iq)

                // output (off the recurrence chain)
                float stress = fmaf(iw18, sumf, fmaf(iwv, m, b3iw));
                keep  = (lane == u) ? stress : keep;
                mprev = m;
            }
        }

        // dump window traces (all 32 lanes); prefetch next x (warp 3)
        sh_tr[buf][w][lane] = keep;
        if (w == 3 && t0 + 32 < TLEN)
            sh_x[buf ^ 1][lane] = x2[b * TLEN + t0 + 32 + lane];
        __syncthreads();

        // mixing head: warp 0, one t per lane
        if (w == 0) {
            float y0 = sh_tr[buf][0][lane];
            float y1 = sh_tr[buf][1][lane];
            float y2 = sh_tr[buf][2][lane];
            float y3 = sh_tr[buf][3][lane];
            float o = bf2_sh;
#pragma unroll
            for (int f = 0; f < 16; f++) {
                float hm = bf1_sh[f];
                hm = fmaf(a_sh[f][0], y0, hm);
                hm = fmaf(a_sh[f][1], y1, hm);
                hm = fmaf(a_sh[f][2], y2, hm);
                hm = fmaf(a_sh[f][3], y3, hm);
                o = fmaf(wf2_sh[f], fmaxf(hm, 0.0f), o);
            }
            out[p * BT + b * TLEN + t0 + lane] = o;
        }
        // sh_tr/sh_x double-buffered: next overwrite of each buffer is
        // separated by the NEXT window's __syncthreads.
    }
}

// ---------------------------------------------------------------------------
extern "C" void kernel_launch(void* const* d_in, const int* in_sizes, int n_in,
                              void* d_out, int out_size) {
    const float* x    = (const float*)d_in[0];
    const float* W1   = (const float*)d_in[1];
    const float* b1   = (const float*)d_in[2];
    const float* W2   = (const float*)d_in[3];
    const float* b2   = (const float*)d_in[4];
    const float* W3   = (const float*)d_in[5];
    const float* b3   = (const float*)d_in[6];
    const float* logE = (const float*)d_in[7];
    const float* loge = (const float*)d_in[8];
    const float* imp  = (const float*)d_in[9];
    const float* lw   = (const float*)d_in[10];
    const float* Wf1  = (const float*)d_in[11];
    const float* bf1  = (const float*)d_in[12];
    const float* Wf2  = (const float*)d_in[13];
    const float* bf2  = (const float*)d_in[14];
    float* out = (float*)d_out;

    pinn_fused_kernel<<<BATCH * 4, 128>>>(x, W1, b1, W2, b2, W3, b3,
                                          logE, loge, imp, lw, Wf1, bf1,
                                          Wf2, bf2, out);
}

// round 13
// speedup vs baseline: 1.9266x; 1.0455x over previous
#include <cuda_runtime.h>

#define BATCH 256
#define TLEN  4096
#define BT    (BATCH * TLEN)

typedef unsigned long long u64;

#define FIXSCALE  262144.0f            // 2^18
#define FIXINV    (1.0f / 262144.0f)
#define MAGICF    12582912.0f          // 1.5 * 2^23
// 32 * 0x4B400000 mod 2^32 = 0x68000000 ; 0x68000000 - 0x4B400000 = 0x1CC00000
#define BIAS_SUB  0x1CC00000

__device__ __forceinline__ float tanh_mufu(float v) {
    float r;
    asm("tanh.approx.f32 %0, %1;" : "=f"(r) : "f"(v));
    return r;
}
__device__ __forceinline__ u64 pack2(float lo, float hi) {
    u64 r; asm("mov.b64 %0, {%1, %2};" : "=l"(r) : "f"(lo), "f"(hi)); return r;
}
__device__ __forceinline__ void unpack2(u64 v, float& lo, float& hi) {
    asm("mov.b64 {%0, %1}, %2;" : "=f"(lo), "=f"(hi) : "l"(v));
}
__device__ __forceinline__ u64 fma2(u64 a, u64 b, u64 c) {
    u64 d; asm("fma.rn.f32x2 %0, %1, %2, %3;" : "=l"(d) : "l"(a), "l"(b), "l"(c)); return d;
}
__device__ __forceinline__ u64 add2(u64 a, u64 b) {
    u64 d; asm("add.rn.f32x2 %0, %1, %2;" : "=l"(d) : "l"(a), "l"(b)); return d;
}

// ---------------------------------------------------------------------------
// Fully fused kernel, v5: R12 winner with three chain/issue cuts:
//   1. NO per-step __syncwarp: the inner loop is divergence-free, so the
//      warp issues every instruction for all lanes together and the LSU
//      services same-warp wavefronts in order (STS then LDS). The WAR
//      direction is made formally safe by PARITY double-buffering sh_h1
//      (buffer = step&1, compile-time in the unrolled body). The full-mask
//      shfl/redux each step re-converge lanes regardless.
//   2. The recurrence carries the BIASED magic sum (sumf_b = MAGICF + sum);
//      -Al18*MAGICF / -iw18*MAGICF are folded into the h1/output biases, so
//      the post-redux FADD disappears from the critical path.
//   3. Stress is computed once per 32-step window from kept (sumf_b, m)
//      pairs (2 SELs/step instead of 2 FMA + SEL).
// Structure unchanged: 1024 blocks x 128 thr, block = (batch, p-output),
// warp = one neuron = one layer, in-block mixing head, magic-bias
// fixed-point redux (R12), half-split h2 dot + mask-16 shfl combine (R10).
// ---------------------------------------------------------------------------
__global__ void __launch_bounds__(128, 7) pinn_fused_kernel(
    const float* __restrict__ x,      // (B, T, 2)
    const float* __restrict__ W1,     // (16, 32, 3)
    const float* __restrict__ b1,     // (16, 32)
    const float* __restrict__ W2,     // (16, 16, 32)
    const float* __restrict__ b2,     // (16, 16)
    const float* __restrict__ W3,     // (16, 1, 16)
    const float* __restrict__ b3,     // (16, 1)
    const float* __restrict__ logE,   // (16, 1)
    const float* __restrict__ logeta, // (16, 1)
    const float* __restrict__ imp,    // (16, 1)
    const float* __restrict__ lw,     // (4,)
    const float* __restrict__ Wf1,    // (16, 4)
    const float* __restrict__ bf1,    // (16,)
    const float* __restrict__ Wf2,    // (1, 16)
    const float* __restrict__ bf2,    // (1,)
    float* __restrict__ out)          // (4, B, T)
{
    const int bx   = blockIdx.x;
    const int b    = bx >> 2;
    const int p    = bx & 3;
    const int tid  = threadIdx.x;
    const int w    = tid >> 5;          // warp 0..3 == layer
    const int lane = tid & 31;
    const int r    = lane & 15;         // h2 row this lane serves
    const int half = lane >> 4;         // which 16-wide half of the dot
    const int n    = (w << 2) | p;      // neuron; n/4 == w (layer)

    // ---- per-lane weights (registers) ----
    const float* W1n = W1 + n * 96;     // (32,3); lane owns h1 row `lane`
    const float w10 = W1n[lane * 3 + 0];
    const float w11 = W1n[lane * 3 + 1];
    const float w12 = W1n[lane * 3 + 2];

    u64 w2h[8];                         // W2[n][r][half*16 .. +15] as 8 f32x2
    {
        const float4* q = (const float4*)(W2 + n * 512 + r * 32 + half * 16);
#pragma unroll
        for (int k = 0; k < 4; k++) {
            float4 v = q[k];
            w2h[2 * k + 0] = pack2(v.x, v.y);
            w2h[2 * k + 1] = pack2(v.z, v.w);
        }
    }
    const float b2r = b2[n * 16 + r];
    const u64 accInit = (half == 0) ? pack2(b2r, 0.0f) : pack2(0.0f, 0.0f);
    // 0.5 (full-warp redux double-counts halves) * 2^18 folded into w3:
    const float w3s  = 0.5f * FIXSCALE * W3[n * 16 + r];
    const float b3n  = b3[n];
    const float Ev   = expf(logE[n]);
    const float etav = expf(logeta[n]);
    const float iwv  = 1.0f / (1.0f + expf(-imp[n]));
    const float Al   = w12 * iwv;              // prev-coupling, folded
    const float Al18 = Al * FIXINV;            // applied to the scaled sum
    const float iw18 = iwv * FIXINV;
    // biased-sum folds: consumer sees sumf_b = MAGICF + sum
    const float b1l2 = b1[n * 32 + lane] + Al * b3n - Al18 * MAGICF;
    const float b3iw = b3n * iwv - iw18 * MAGICF;

    // ---- shared memory (tiny) ----
    __shared__ __align__(16) float  sh_h1[4][2][32]; // [warp][parity][lane]
    __shared__ __align__(16) float2 sh_x[2][32];     // double-buffered x window
    __shared__ float  sh_tr[2][4][32];               // [buf][layer][t] traces
    __shared__ float  a_sh[16][4];                   // mixing consts
    __shared__ float  wf2_sh[16];
    __shared__ float  bf1_sh[16];
    __shared__ float  bf2_sh;

    const float2* x2 = (const float2*)x;

    if (tid < 16) {
        const int f = tid;
        float mx = fmaxf(fmaxf(lw[0], lw[1]), fmaxf(lw[2], lw[3]));
        float e0 = expf(lw[0] - mx), e1 = expf(lw[1] - mx);
        float e2 = expf(lw[2] - mx), e3 = expf(lw[3] - mx);
        float es = e0 + e1 + e2 + e3;
        float wl[4] = { e0 / es, e1 / es, e2 / es, e3 / es };
#pragma unroll
        for (int l = 0; l < 4; l++) {
            float s = 0.0f;
#pragma unroll
            for (int pp = 0; pp < 4; pp++)
                s += 1.0f / (1.0f + expf(-imp[l * 4 + pp]));
            float S = s / (s + 1e-8f);
            a_sh[f][l] = Wf1[f * 4 + l] * (S * wl[l]);
        }
        wf2_sh[f] = Wf2[f];
        bf1_sh[f] = bf1[f];
        if (f == 0) bf2_sh = bf2[0];
    }
    if (tid < 32) sh_x[0][tid] = x2[b * TLEN + tid];   // stage first window
    __syncthreads();

    float sumf_b = MAGICF;  // biased carried sum (value = MAGICF + 0)
    float mprev  = -b3n;    // carried maxwell term; cancels folded Al*b3n at u=0
    float keep_s = MAGICF;  // kept (biased sum, m) for the lane's step
    float keep_m = 0.0f;

    for (int t0 = 0; t0 < TLEN; t0 += 32) {
        const int buf = (t0 >> 5) & 1;
        const float4* xw4 = (const float4*)&sh_x[buf][0];

#pragma unroll
        for (int v2i = 0; v2i < 16; v2i++) {        // 2 timesteps per iter
            float4 xx = xw4[v2i];                    // broadcast LDS.128
#pragma unroll
            for (int s = 0; s < 2; s++) {            // s == step parity
                const int   u      = 2 * v2i + s;
                const float strain = s ? xx.z : xx.x;
                const float rate   = s ? xx.w : xx.y;

                // off-path work (b3n and -Al18*MAGICF pre-folded into b1l2)
                float m  = fmaf(Ev, strain, etav * rate);
                float zo = fmaf(Al, mprev,
                                fmaf(w11, rate, fmaf(w10, strain, b1l2)));

                // ---- critical path: sumf_b -> z -> tanh -> h2 -> redux ----
                float h = tanh_mufu(fmaf(Al18, sumf_b, zo));

                sh_h1[w][s][lane] = h;
                // no syncwarp: divergence-free warp => lockstep issue;
                // LSU services the STS wavefront before the later LDS.
                // WAR across steps is covered by the parity buffers.

                const float4* h4 = (const float4*)&sh_h1[w][s][half * 16];
                float4 v0 = h4[0], v1 = h4[1], v2 = h4[2], v3 = h4[3];
                u64 a0 = accInit, a1 = 0;
                a0 = fma2(w2h[0], pack2(v0.x, v0.y), a0);
                a1 = fma2(w2h[1], pack2(v0.z, v0.w), a1);
                a0 = fma2(w2h[2], pack2(v1.x, v1.y), a0);
                a1 = fma2(w2h[3], pack2(v1.z, v1.w), a1);
                a0 = fma2(w2h[4], pack2(v2.x, v2.y), a0);
                a1 = fma2(w2h[5], pack2(v2.z, v2.w), a1);
                a0 = fma2(w2h[6], pack2(v3.x, v3.y), a0);
                a1 = fma2(w2h[7], pack2(v3.z, v3.w), a1);
                float lo, hi;
                unpack2(add2(a0, a1), lo, hi);
                float ph = lo + hi;                  // 16-wide half dot
                // combine halves: lanes r and r+16 now bitwise-identical
                float full = ph + __shfl_xor_sync(0xffffffffu, ph, 16);
                float h2v = tanh_mufu(full);

                // magic-bias fixed point; redux sums biases modularly
                int ib = __float_as_int(fmaf(w3s, h2v, MAGICF));
                int is = __reduce_add_sync(0xffffffffu, ib);
                sumf_b = __int_as_float(is - BIAS_SUB);   // MAGICF + sum

                // keep this step's state for the window epilogue
                keep_s = (lane == u) ? sumf_b : keep_s;
                keep_m = (lane == u) ? m      : keep_m;
                mprev  = m;
            }
        }

        // window epilogue: reconstruct stress, dump traces, prefetch x
        float stress = fmaf(iw18, keep_s, fmaf(iwv, keep_m, b3iw));
        sh_tr[buf][w][lane] = stress;
        if (w == 3 && t0 + 32 < TLEN)
            sh_x[buf ^ 1][lane] = x2[b * TLEN + t0 + 32 + lane];
        __syncthreads();

        // mixing head: warp 0, one t per lane
        if (w == 0) {
            float y0 = sh_tr[buf][0][lane];
            float y1 = sh_tr[buf][1][lane];
            float y2 = sh_tr[buf][2][lane];
            float y3 = sh_tr[buf][3][lane];
            float o = bf2_sh;
#pragma unroll
            for (int f = 0; f < 16; f++) {
                float hm = bf1_sh[f];
                hm = fmaf(a_sh[f][0], y0, hm);
                hm = fmaf(a_sh[f][1], y1, hm);
                hm = fmaf(a_sh[f][2], y2, hm);
                hm = fmaf(a_sh[f][3], y3, hm);
                o = fmaf(wf2_sh[f], fmaxf(hm, 0.0f), o);
            }
            out[p * BT + b * TLEN + t0 + lane] = o;
        }
        // sh_tr/sh_x double-buffered: next overwrite of each buffer is
        // separated by the NEXT window's __syncthreads.
    }
}

// ---------------------------------------------------------------------------
extern "C" void kernel_launch(void* const* d_in, const int* in_sizes, int n_in,
                              void* d_out, int out_size) {
    const float* x    = (const float*)d_in[0];
    const float* W1   = (const float*)d_in[1];
    const float* b1   = (const float*)d_in[2];
    const float* W2   = (const float*)d_in[3];
    const float* b2   = (const float*)d_in[4];
    const float* W3   = (const float*)d_in[5];
    const float* b3   = (const float*)d_in[6];
    const float* logE = (const float*)d_in[7];
    const float* loge = (const float*)d_in[8];
    const float* imp  = (const float*)d_in[9];
    const float* lw   = (const float*)d_in[10];
    const float* Wf1  = (const float*)d_in[11];
    const float* bf1  = (const float*)d_in[12];
    const float* Wf2  = (const float*)d_in[13];
    const float* bf2  = (const float*)d_in[14];
    float* out = (float*)d_out;

    pinn_fused_kernel<<<BATCH * 4, 128>>>(x, W1, b1, W2, b2, W3, b3,
                                          logE, loge, imp, lw, Wf1, bf1,
                                          Wf2, bf2, out);
}

// round 14
// speedup vs baseline: 1.9342x; 1.0039x over previous
#include <cuda_runtime.h>

#define BATCH 256
#define TLEN  4096
#define BT    (BATCH * TLEN)

typedef unsigned long long u64;

#define FIXSCALE  262144.0f            // 2^18
#define FIXINV    (1.0f / 262144.0f)
#define MAGICF    12582912.0f          // 1.5 * 2^23
// 32 * 0x4B400000 mod 2^32 = 0x68000000 ; 0x68000000 - 0x4B400000 = 0x1CC00000
#define BIAS_SUB  0x1CC00000

__device__ __forceinline__ float tanh_mufu(float v) {
    float r;
    asm("tanh.approx.f32 %0, %1;" : "=f"(r) : "f"(v));
    return r;
}
__device__ __forceinline__ u64 pack2(float lo, float hi) {
    u64 r; asm("mov.b64 %0, {%1, %2};" : "=l"(r) : "f"(lo), "f"(hi)); return r;
}
__device__ __forceinline__ void unpack2(u64 v, float& lo, float& hi) {
    asm("mov.b64 {%0, %1}, %2;" : "=f"(lo), "=f"(hi) : "l"(v));
}
__device__ __forceinline__ u64 fma2(u64 a, u64 b, u64 c) {
    u64 d; asm("fma.rn.f32x2 %0, %1, %2, %3;" : "=l"(d) : "l"(a), "l"(b), "l"(c)); return d;
}
__device__ __forceinline__ u64 mul2(u64 a, u64 b) {
    u64 d; asm("mul.rn.f32x2 %0, %1, %2;" : "=l"(d) : "l"(a), "l"(b)); return d;
}
__device__ __forceinline__ u64 add2(u64 a, u64 b) {
    u64 d; asm("add.rn.f32x2 %0, %1, %2;" : "=l"(d) : "l"(a), "l"(b)); return d;
}

// ---------------------------------------------------------------------------
// Fully fused kernel, v6: R13 winner with issue-side trims (MIO is the wall
// at ~74%; shaving non-MIO instructions lets warps reach their MIO ops
// sooner):
//   - keep_m + its per-step SEL removed: the window epilogue recomputes the
//     lane-step's maxwell term from sh_x[buf][lane] (2 FMA per window).
//   - a1 accumulator head is mul2 (no zero-init mov); a0 chains accInit
//     through the first fma2.
// Everything else frozen from R13: no per-step syncwarp (divergence-free
// warp + parity-buffered sh_h1), biased magic-sum carry, magic-bias
// fixed-point redux, half-split h2 dot + mask-16 shfl combine, in-block
// mixing head. 1024 blocks x 128 thr; block = (batch, p-output);
// warp = one neuron = one layer.
// ---------------------------------------------------------------------------
__global__ void __launch_bounds__(128, 7) pinn_fused_kernel(
    const float* __restrict__ x,      // (B, T, 2)
    const float* __restrict__ W1,     // (16, 32, 3)
    const float* __restrict__ b1,     // (16, 32)
    const float* __restrict__ W2,     // (16, 16, 32)
    const float* __restrict__ b2,     // (16, 16)
    const float* __restrict__ W3,     // (16, 1, 16)
    const float* __restrict__ b3,     // (16, 1)
    const float* __restrict__ logE,   // (16, 1)
    const float* __restrict__ logeta, // (16, 1)
    const float* __restrict__ imp,    // (16, 1)
    const float* __restrict__ lw,     // (4,)
    const float* __restrict__ Wf1,    // (16, 4)
    const float* __restrict__ bf1,    // (16,)
    const float* __restrict__ Wf2,    // (1, 16)
    const float* __restrict__ bf2,    // (1,)
    float* __restrict__ out)          // (4, B, T)
{
    const int bx   = blockIdx.x;
    const int b    = bx >> 2;
    const int p    = bx & 3;
    const int tid  = threadIdx.x;
    const int w    = tid >> 5;          // warp 0..3 == layer
    const int lane = tid & 31;
    const int r    = lane & 15;         // h2 row this lane serves
    const int half = lane >> 4;         // which 16-wide half of the dot
    const int n    = (w << 2) | p;      // neuron; n/4 == w (layer)

    // ---- per-lane weights (registers) ----
    const float* W1n = W1 + n * 96;     // (32,3); lane owns h1 row `lane`
    const float w10 = W1n[lane * 3 + 0];
    const float w11 = W1n[lane * 3 + 1];
    const float w12 = W1n[lane * 3 + 2];

    u64 w2h[8];                         // W2[n][r][half*16 .. +15] as 8 f32x2
    {
        const float4* q = (const float4*)(W2 + n * 512 + r * 32 + half * 16);
#pragma unroll
        for (int k = 0; k < 4; k++) {
            float4 v = q[k];
            w2h[2 * k + 0] = pack2(v.x, v.y);
            w2h[2 * k + 1] = pack2(v.z, v.w);
        }
    }
    const float b2r = b2[n * 16 + r];
    const u64 accInit = (half == 0) ? pack2(b2r, 0.0f) : pack2(0.0f, 0.0f);
    // 0.5 (full-warp redux double-counts halves) * 2^18 folded into w3:
    const float w3s  = 0.5f * FIXSCALE * W3[n * 16 + r];
    const float b3n  = b3[n];
    const float Ev   = expf(logE[n]);
    const float etav = expf(logeta[n]);
    const float iwv  = 1.0f / (1.0f + expf(-imp[n]));
    const float Al   = w12 * iwv;              // prev-coupling, folded
    const float Al18 = Al * FIXINV;            // applied to the scaled sum
    const float iw18 = iwv * FIXINV;
    // biased-sum folds: consumer sees sumf_b = MAGICF + sum
    const float b1l2 = b1[n * 32 + lane] + Al * b3n - Al18 * MAGICF;
    const float b3iw = b3n * iwv - iw18 * MAGICF;

    // ---- shared memory (tiny) ----
    __shared__ __align__(16) float  sh_h1[4][2][32]; // [warp][parity][lane]
    __shared__ __align__(16) float2 sh_x[2][32];     // double-buffered x window
    __shared__ float  sh_tr[2][4][32];               // [buf][layer][t] traces
    __shared__ float  a_sh[16][4];                   // mixing consts
    __shared__ float  wf2_sh[16];
    __shared__ float  bf1_sh[16];
    __shared__ float  bf2_sh;

    const float2* x2 = (const float2*)x;

    if (tid < 16) {
        const int f = tid;
        float mx = fmaxf(fmaxf(lw[0], lw[1]), fmaxf(lw[2], lw[3]));
        float e0 = expf(lw[0] - mx), e1 = expf(lw[1] - mx);
        float e2 = expf(lw[2] - mx), e3 = expf(lw[3] - mx);
        float es = e0 + e1 + e2 + e3;
        float wl[4] = { e0 / es, e1 / es, e2 / es, e3 / es };
#pragma unroll
        for (int l = 0; l < 4; l++) {
            float s = 0.0f;
#pragma unroll
            for (int pp = 0; pp < 4; pp++)
                s += 1.0f / (1.0f + expf(-imp[l * 4 + pp]));
            float S = s / (s + 1e-8f);
            a_sh[f][l] = Wf1[f * 4 + l] * (S * wl[l]);
        }
        wf2_sh[f] = Wf2[f];
        bf1_sh[f] = bf1[f];
        if (f == 0) bf2_sh = bf2[0];
    }
    if (tid < 32) sh_x[0][tid] = x2[b * TLEN + tid];   // stage first window
    __syncthreads();

    float sumf_b = MAGICF;  // biased carried sum (value = MAGICF + 0)
    float mprev  = -b3n;    // carried maxwell term; cancels folded Al*b3n at u=0
    float keep_s = MAGICF;  // kept biased sum for the lane's step

    for (int t0 = 0; t0 < TLEN; t0 += 32) {
        const int buf = (t0 >> 5) & 1;
        const float4* xw4 = (const float4*)&sh_x[buf][0];

#pragma unroll
        for (int v2i = 0; v2i < 16; v2i++) {        // 2 timesteps per iter
            float4 xx = xw4[v2i];                    // broadcast LDS.128
#pragma unroll
            for (int s = 0; s < 2; s++) {            // s == step parity
                const int   u      = 2 * v2i + s;
                const float strain = s ? xx.z : xx.x;
                const float rate   = s ? xx.w : xx.y;

                // off-path work (b3n and -Al18*MAGICF pre-folded into b1l2)
                float m  = fmaf(Ev, strain, etav * rate);
                float zo = fmaf(Al, mprev,
                                fmaf(w11, rate, fmaf(w10, strain, b1l2)));

                // ---- critical path: sumf_b -> z -> tanh -> h2 -> redux ----
                float h = tanh_mufu(fmaf(Al18, sumf_b, zo));

                sh_h1[w][s][lane] = h;
                // no syncwarp: divergence-free warp => lockstep issue;
                // LSU services the STS wavefront before the later LDS.
                // WAR across steps is covered by the parity buffers.

                const float4* h4 = (const float4*)&sh_h1[w][s][half * 16];
                float4 v0 = h4[0], v1 = h4[1], v2 = h4[2], v3 = h4[3];
                u64 a0 = fma2(w2h[0], pack2(v0.x, v0.y), accInit);
                u64 a1 = mul2(w2h[1], pack2(v0.z, v0.w));
                a0 = fma2(w2h[2], pack2(v1.x, v1.y), a0);
                a1 = fma2(w2h[3], pack2(v1.z, v1.w), a1);
                a0 = fma2(w2h[4], pack2(v2.x, v2.y), a0);
                a1 = fma2(w2h[5], pack2(v2.z, v2.w), a1);
                a0 = fma2(w2h[6], pack2(v3.x, v3.y), a0);
                a1 = fma2(w2h[7], pack2(v3.z, v3.w), a1);
                float lo, hi;
                unpack2(add2(a0, a1), lo, hi);
                float ph = lo + hi;                  // 16-wide half dot
                // combine halves: lanes r and r+16 now bitwise-identical
                float full = ph + __shfl_xor_sync(0xffffffffu, ph, 16);
                float h2v = tanh_mufu(full);

                // magic-bias fixed point; redux sums biases modularly
                int ib = __float_as_int(fmaf(w3s, h2v, MAGICF));
                int is = __reduce_add_sync(0xffffffffu, ib);
                sumf_b = __int_as_float(is - BIAS_SUB);   // MAGICF + sum

                // keep only the biased sum; m is recomputed in the epilogue
                keep_s = (lane == u) ? sumf_b : keep_s;
                mprev  = m;
            }
        }

        // window epilogue: lane u recomputes its step's maxwell term from
        // its own staged x, reconstructs stress, dumps the trace.
        {
            float2 xl = sh_x[buf][lane];
            float ml  = fmaf(Ev, xl.x, etav * xl.y);
            float stress = fmaf(iw18, keep_s, fmaf(iwv, ml, b3iw));
            sh_tr[buf][w][lane] = stress;
        }
        if (w == 3 && t0 + 32 < TLEN)
            sh_x[buf ^ 1][lane] = x2[b * TLEN + t0 + 32 + lane];
        __syncthreads();

        // mixing head: warp 0, one t per lane
        if (w == 0) {
            float y0 = sh_tr[buf][0][lane];
            float y1 = sh_tr[buf][1][lane];
            float y2 = sh_tr[buf][2][lane];
            float y3 = sh_tr[buf][3][lane];
            float o = bf2_sh;
#pragma unroll
            for (int f = 0; f < 16; f++) {
                float hm = bf1_sh[f];
                hm = fmaf(a_sh[f][0], y0, hm);
                hm = fmaf(a_sh[f][1], y1, hm);
                hm = fmaf(a_sh[f][2], y2, hm);
                hm = fmaf(a_sh[f][3], y3, hm);
                o = fmaf(wf2_sh[f], fmaxf(hm, 0.0f), o);
            }
            out[p * BT + b * TLEN + t0 + lane] = o;
        }
        // sh_tr/sh_x double-buffered: next overwrite of each buffer is
        // separated by the NEXT window's __syncthreads.
    }
}

// ---------------------------------------------------------------------------
extern "C" void kernel_launch(void* const* d_in, const int* in_sizes, int n_in,
                              void* d_out, int out_size) {
    const float* x    = (const float*)d_in[0];
    const float* W1   = (const float*)d_in[1];
    const float* b1   = (const float*)d_in[2];
    const float* W2   = (const float*)d_in[3];
    const float* b2   = (const float*)d_in[4];
    const float* W3   = (const float*)d_in[5];
    const float* b3   = (const float*)d_in[6];
    const float* logE = (const float*)d_in[7];
    const float* loge = (const float*)d_in[8];
    const float* imp  = (const float*)d_in[9];
    const float* lw   = (const float*)d_in[10];
    const float* Wf1  = (const float*)d_in[11];
    const float* bf1  = (const float*)d_in[12];
    const float* Wf2  = (const float*)d_in[13];
    const float* bf2  = (const float*)d_in[14];
    float* out = (float*)d_out;

    pinn_fused_kernel<<<BATCH * 4, 128>>>(x, W1, b1, W2, b2, W3, b3,
                                          logE, loge, imp, lw, Wf1, bf1,
                                          Wf2, bf2, out);
}

// round 15
// speedup vs baseline: 2.2881x; 1.1830x over previous
#include <cuda_runtime.h>
#include <cuda_fp16.h>

#define BATCH 256
#define TLEN  4096
#define BT    (BATCH * TLEN)

#define FIXSCALE  262144.0f            // 2^18
#define FIXINV    (1.0f / 262144.0f)
#define MAGICF    12582912.0f          // 1.5 * 2^23
// 32 * 0x4B400000 mod 2^32 = 0x68000000 ; 0x68000000 - 0x4B400000 = 0x1CC00000
#define BIAS_SUB  0x1CC00000

__device__ __forceinline__ float tanh_mufu(float v) {
    float r;
    asm("tanh.approx.f32 %0, %1;" : "=f"(r) : "f"(v));
    return r;
}
__device__ __forceinline__ unsigned pack_h2(float lo, float hi) {
    __half2 v = __floats2half2_rn(lo, hi);   // lo -> low half, hi -> high half
    return *reinterpret_cast<unsigned*>(&v);
}
// D = A(16x16 f16) x B(16x8 f16) + C, fp32 accumulate.
__device__ __forceinline__ void mma16816(
    float& d0, float& d1, float& d2, float& d3,
    unsigned a0, unsigned a1, unsigned a2, unsigned a3,
    unsigned b0, unsigned b1,
    float c0, float c1, float c2, float c3)
{
    asm volatile(
        "mma.sync.aligned.m16n8k16.row.col.f32.f16.f16.f32 "
        "{%0,%1,%2,%3}, {%4,%5,%6,%7}, {%8,%9}, {%10,%11,%12,%13};"
        : "=f"(d0), "=f"(d1), "=f"(d2), "=f"(d3)
        : "r"(a0), "r"(a1), "r"(a2), "r"(a3), "r"(b0), "r"(b1),
          "f"(c0), "f"(c1), "f"(c2), "f"(c3));
}

// ---------------------------------------------------------------------------
// Fully fused kernel, v7: the h2 16x32 matvec moves to the TENSOR pipe.
// MIO was the wall (L1 75.5%, ~7.5 smem-class ops/step); now the exchange is
//   tanh -> F2FP -> 1x STS.16 (permuted slot) -> 1x broadcast LDS.128
// whose four words ARE the B-fragments of two m16n8k16 HMMAs (W2 preloaded
// as A-fragments, b2 bias preloaded as the C accumulator; h broadcast into
// all 8 B columns so every thread's d0/d2 hold preact rows g, g+8).
// fp16 rounds W2 and h (fp32 accumulate): predicted rel_err ~2-4e-4 (<1e-3).
// Everything else frozen from R14: no per-step syncwarp (divergence-free
// warp + parity buffers), biased magic-sum carry + s32 redux (x4 row
// duplication folded as 0.25 into w3s), window-32 epilogue, in-block mixing
// head. 1024 blocks x 128 thr; block = (batch, p-output); warp = neuron.
// ---------------------------------------------------------------------------
__global__ void __launch_bounds__(128, 7) pinn_fused_kernel(
    const float* __restrict__ x,      // (B, T, 2)
    const float* __restrict__ W1,     // (16, 32, 3)
    const float* __restrict__ b1,     // (16, 32)
    const float* __restrict__ W2,     // (16, 16, 32)
    const float* __restrict__ b2,     // (16, 16)
    const float* __restrict__ W3,     // (16, 1, 16)
    const float* __restrict__ b3,     // (16, 1)
    const float* __restrict__ logE,   // (16, 1)
    const float* __restrict__ logeta, // (16, 1)
    const float* __restrict__ imp,    // (16, 1)
    const float* __restrict__ lw,     // (4,)
    const float* __restrict__ Wf1,    // (16, 4)
    const float* __restrict__ bf1,    // (16,)
    const float* __restrict__ Wf2,    // (1, 16)
    const float* __restrict__ bf2,    // (1,)
    float* __restrict__ out)          // (4, B, T)
{
    const int bx   = blockIdx.x;
    const int b    = bx >> 2;
    const int p    = bx & 3;
    const int tid  = threadIdx.x;
    const int w    = tid >> 5;          // warp 0..3 == layer
    const int lane = tid & 31;
    const int g    = lane >> 2;         // MMA row base (this thread: rows g, g+8)
    const int t4   = lane & 3;          // thread-in-group (k-slice selector)
    const int n    = (w << 2) | p;      // neuron; n/4 == w (layer)

    // ---- per-lane h1 weights ----
    const float* W1n = W1 + n * 96;     // (32,3); lane owns h1 row `lane`
    const float w10 = W1n[lane * 3 + 0];
    const float w11 = W1n[lane * 3 + 1];
    const float w12 = W1n[lane * 3 + 2];

    // ---- W2 as A-fragments for two m16n8k16 MMAs (k 0-15, 16-31) ----
    // A frag reg layout: r0={row g,cols 2t,2t+1} r1={row g+8,same}
    //                    r2={row g,cols 2t+8,+9} r3={row g+8,same}
    const float* W2n = W2 + n * 512;    // (16,32) row-major
    unsigned A1[4], A2[4];
    {
        const float* rg  = W2n + g * 32;
        const float* rg8 = W2n + (g + 8) * 32;
        const int c = 2 * t4;
        A1[0] = pack_h2(rg [c],      rg [c + 1]);
        A1[1] = pack_h2(rg8[c],      rg8[c + 1]);
        A1[2] = pack_h2(rg [c + 8],  rg [c + 9]);
        A1[3] = pack_h2(rg8[c + 8],  rg8[c + 9]);
        A2[0] = pack_h2(rg [c + 16], rg [c + 17]);
        A2[1] = pack_h2(rg8[c + 16], rg8[c + 17]);
        A2[2] = pack_h2(rg [c + 24], rg [c + 25]);
        A2[3] = pack_h2(rg8[c + 24], rg8[c + 25]);
    }
    const float c0i = b2[n * 16 + g];       // C-frag bias (rows g / g+8)
    const float c2i = b2[n * 16 + g + 8];
    // 0.25: full-warp redux quadruple-counts (4 col-duplicate threads/row)
    const float w3sa = 0.25f * FIXSCALE * W3[n * 16 + g];
    const float w3sb = 0.25f * FIXSCALE * W3[n * 16 + g + 8];

    const float b3n  = b3[n];
    const float Ev   = expf(logE[n]);
    const float etav = expf(logeta[n]);
    const float iwv  = 1.0f / (1.0f + expf(-imp[n]));
    const float Al   = w12 * iwv;              // prev-coupling, folded
    const float Al18 = Al * FIXINV;            // applied to the scaled sum
    const float iw18 = iwv * FIXINV;
    // biased-sum folds: consumer sees sumf_b = MAGICF + sum
    const float b1l2 = b1[n * 32 + lane] + Al * b3n - Al18 * MAGICF;
    const float b3iw = b3n * iwv - iw18 * MAGICF;

    // permuted fp16 slot so one LDS.128 returns both MMAs' B-fragments:
    // half-index = 8*((l>>1)&3) + 2*(l>>3) + (l&1)
    const int hidx = 8 * ((lane >> 1) & 3) + 2 * (lane >> 3) + (lane & 1);

    // ---- shared memory (tiny) ----
    __shared__ __align__(16) __half sh_hh[4][2][32]; // [warp][parity][slot]
    __shared__ __align__(16) float2 sh_x[2][32];     // double-buffered x window
    __shared__ float  sh_tr[2][4][32];               // [buf][layer][t] traces
    __shared__ float  a_sh[16][4];                   // mixing consts
    __shared__ float  wf2_sh[16];
    __shared__ float  bf1_sh[16];
    __shared__ float  bf2_sh;

    const float2* x2 = (const float2*)x;

    if (tid < 16) {
        const int f = tid;
        float mx = fmaxf(fmaxf(lw[0], lw[1]), fmaxf(lw[2], lw[3]));
        float e0 = expf(lw[0] - mx), e1 = expf(lw[1] - mx);
        float e2 = expf(lw[2] - mx), e3 = expf(lw[3] - mx);
        float es = e0 + e1 + e2 + e3;
        float wl[4] = { e0 / es, e1 / es, e2 / es, e3 / es };
#pragma unroll
        for (int l = 0; l < 4; l++) {
            float s = 0.0f;
#pragma unroll
            for (int pp = 0; pp < 4; pp++)
                s += 1.0f / (1.0f + expf(-imp[l * 4 + pp]));
            float S = s / (s + 1e-8f);
            a_sh[f][l] = Wf1[f * 4 + l] * (S * wl[l]);
        }
        wf2_sh[f] = Wf2[f];
        bf1_sh[f] = bf1[f];
        if (f == 0) bf2_sh = bf2[0];
    }
    if (tid < 32) sh_x[0][tid] = x2[b * TLEN + tid];   // stage first window
    __syncthreads();

    float sumf_b = MAGICF;  // biased carried sum (value = MAGICF + 0)
    float mprev  = -b3n;    // carried maxwell term; cancels folded Al*b3n at u=0
    float keep_s = MAGICF;  // kept biased sum for the lane's step

    for (int t0 = 0; t0 < TLEN; t0 += 32) {
        const int buf = (t0 >> 5) & 1;
        const float4* xw4 = (const float4*)&sh_x[buf][0];

#pragma unroll
        for (int v2i = 0; v2i < 16; v2i++) {        // 2 timesteps per iter
            float4 xx = xw4[v2i];                    // broadcast LDS.128
#pragma unroll
            for (int s = 0; s < 2; s++) {            // s == step parity
                const int   u      = 2 * v2i + s;
                const float strain = s ? xx.z : xx.x;
                const float rate   = s ? xx.w : xx.y;

                // off-path work (b3n and -Al18*MAGICF pre-folded into b1l2)
                float m  = fmaf(Ev, strain, etav * rate);
                float zo = fmaf(Al, mprev,
                                fmaf(w11, rate, fmaf(w10, strain, b1l2)));

                // ---- critical path: sumf_b -> z -> tanh -> exchange ->
                //      2x HMMA -> tanh -> redux ----
                float h = tanh_mufu(fmaf(Al18, sumf_b, zo));

                sh_hh[w][s][hidx] = __float2half_rn(h);   // STS.16, permuted
                // no syncwarp: divergence-free warp => in-order LSU services
                // the store wavefront before the next load; WAR across steps
                // covered by the parity buffers.

                uint4 bb = *(const uint4*)&sh_hh[w][s][8 * t4]; // B frags
                float d0, d1, d2, d3;
                mma16816(d0, d1, d2, d3,
                         A1[0], A1[1], A1[2], A1[3], bb.x, bb.y,
                         c0i, c0i, c2i, c2i);
                mma16816(d0, d1, d2, d3,
                         A2[0], A2[1], A2[2], A2[3], bb.z, bb.w,
                         d0, d1, d2, d3);

                float h2a = tanh_mufu(d0);   // preact row g
                float h2b = tanh_mufu(d2);   // preact row g+8

                // magic-bias fixed point; redux sums biases modularly
                int ib = __float_as_int(fmaf(w3sb, h2b,
                                             fmaf(w3sa, h2a, MAGICF)));
                int is = __reduce_add_sync(0xffffffffu, ib);
                sumf_b = __int_as_float(is - BIAS_SUB);   // MAGICF + sum

                keep_s = (lane == u) ? sumf_b : keep_s;
                mprev  = m;
            }
        }

        // window epilogue: lane u recomputes its step's maxwell term from
        // its own staged x, reconstructs stress, dumps the trace.
        {
            float2 xl = sh_x[buf][lane];
            float ml  = fmaf(Ev, xl.x, etav * xl.y);
            float stress = fmaf(iw18, keep_s, fmaf(iwv, ml, b3iw));
            sh_tr[buf][w][lane] = stress;
        }
        if (w == 3 && t0 + 32 < TLEN)
            sh_x[buf ^ 1][lane] = x2[b * TLEN + t0 + 32 + lane];
        __syncthreads();

        // mixing head: warp 0, one t per lane
        if (w == 0) {
            float y0 = sh_tr[buf][0][lane];
            float y1 = sh_tr[buf][1][lane];
            float y2 = sh_tr[buf][2][lane];
            float y3 = sh_tr[buf][3][lane];
            float o = bf2_sh;
#pragma unroll
            for (int f = 0; f < 16; f++) {
                float hm = bf1_sh[f];
                hm = fmaf(a_sh[f][0], y0, hm);
                hm = fmaf(a_sh[f][1], y1, hm);
                hm = fmaf(a_sh[f][2], y2, hm);
                hm = fmaf(a_sh[f][3], y3, hm);
                o = fmaf(wf2_sh[f], fmaxf(hm, 0.0f), o);
            }
            out[p * BT + b * TLEN + t0 + lane] = o;
        }
        // sh_tr/sh_x double-buffered: next overwrite of each buffer is
        // separated by the NEXT window's __syncthreads.
    }
}

// ---------------------------------------------------------------------------
extern "C" void kernel_launch(void* const* d_in, const int* in_sizes, int n_in,
                              void* d_out, int out_size) {
    const float* x    = (const float*)d_in[0];
    const float* W1   = (const float*)d_in[1];
    const float* b1   = (const float*)d_in[2];
    const float* W2   = (const float*)d_in[3];
    const float* b2   = (const float*)d_in[4];
    const float* W3   = (const float*)d_in[5];
    const float* b3   = (const float*)d_in[6];
    const float* logE = (const float*)d_in[7];
    const float* loge = (const float*)d_in[8];
    const float* imp  = (const float*)d_in[9];
    const float* lw   = (const float*)d_in[10];
    const float* Wf1  = (const float*)d_in[11];
    const float* bf1  = (const float*)d_in[12];
    const float* Wf2  = (const float*)d_in[13];
    const float* bf2  = (const float*)d_in[14];
    float* out = (float*)d_out;

    pinn_fused_kernel<<<BATCH * 4, 128>>>(x, W1, b1, W2, b2, W3, b3,
                                          logE, loge, imp, lw, Wf1, bf1,
                                          Wf2, bf2, out);
}

// round 16
// speedup vs baseline: 2.4533x; 1.0722x over previous
#include <cuda_runtime.h>
#include <cuda_fp16.h>

#define BATCH 256
#define TLEN  4096
#define BT    (BATCH * TLEN)

#define FIXSCALE  262144.0f            // 2^18
#define FIXINV    (1.0f / 262144.0f)
#define MAGICF    12582912.0f          // 1.5 * 2^23
// 32 * 0x4B400000 mod 2^32 = 0x68000000 ; 0x68000000 - 0x4B400000 = 0x1CC00000
#define BIAS_SUB  0x1CC00000

__device__ __forceinline__ float tanh_mufu(float v) {
    float r;
    asm("tanh.approx.f32 %0, %1;" : "=f"(r) : "f"(v));
    return r;
}
__device__ __forceinline__ unsigned pack_h2(float lo, float hi) {
    __half2 v = __floats2half2_rn(lo, hi);   // lo -> low half, hi -> high half
    return *reinterpret_cast<unsigned*>(&v);
}
// D = A(16x16 f16) x B(16x8 f16) + C, fp32 accumulate.
__device__ __forceinline__ void mma16816(
    float& d0, float& d1, float& d2, float& d3,
    unsigned a0, unsigned a1, unsigned a2, unsigned a3,
    unsigned b0, unsigned b1,
    float c0, float c1, float c2, float c3)
{
    asm volatile(
        "mma.sync.aligned.m16n8k16.row.col.f32.f16.f16.f32 "
        "{%0,%1,%2,%3}, {%4,%5,%6,%7}, {%8,%9}, {%10,%11,%12,%13};"
        : "=f"(d0), "=f"(d1), "=f"(d2), "=f"(d3)
        : "r"(a0), "r"(a1), "r"(a2), "r"(a3), "r"(b0), "r"(b1),
          "f"(c0), "f"(c1), "f"(c2), "f"(c3));
}

// ---------------------------------------------------------------------------
// Fully fused kernel, v8: R15 winner (h2 matvec on the tensor pipe via two
// m16n8k16 HMMAs fed by a 1xSTS.16 + 1xLDS.128 fp16 exchange) with two
// overlap-regime cuts (no pipe saturated at 347 cyc/iter; XU=168 / issue=182
// / chain=200 floors all co-binding):
//   1. h2 tanh DEDUP by quad parity: the 4 threads of a quad hold identical
//      d0/d2, so even-t4 lanes tanh row g (d0) and odd lanes row g+8 (d2).
//      MUFU 3->2 per step (XU floor 168->112); redux scale 0.25->0.5 with a
//      mathematically identical sum (2 copies per unique rounded product).
//   2. The two HMMAs are now INDEPENDENT (second C=0) and combined by one
//      FADD after the parity SEL — removes the serial accumulator
//      dependency (~20 cyc) from the chain.
// Everything else frozen from R15: no per-step syncwarp (divergence-free
// warp + parity buffers), biased magic-sum carry + s32 redux, window-32
// epilogue, in-block mixing head. 1024 blocks x 128 thr; block =
// (batch, p-output); warp = one neuron = one layer.
// ---------------------------------------------------------------------------
__global__ void __launch_bounds__(128, 7) pinn_fused_kernel(
    const float* __restrict__ x,      // (B, T, 2)
    const float* __restrict__ W1,     // (16, 32, 3)
    const float* __restrict__ b1,     // (16, 32)
    const float* __restrict__ W2,     // (16, 16, 32)
    const float* __restrict__ b2,     // (16, 16)
    const float* __restrict__ W3,     // (16, 1, 16)
    const float* __restrict__ b3,     // (16, 1)
    const float* __restrict__ logE,   // (16, 1)
    const float* __restrict__ logeta, // (16, 1)
    const float* __restrict__ imp,    // (16, 1)
    const float* __restrict__ lw,     // (4,)
    const float* __restrict__ Wf1,    // (16, 4)
    const float* __restrict__ bf1,    // (16,)
    const float* __restrict__ Wf2,    // (1, 16)
    const float* __restrict__ bf2,    // (1,)
    float* __restrict__ out)          // (4, B, T)
{
    const int bx   = blockIdx.x;
    const int b    = bx >> 2;
    const int p    = bx & 3;
    const int tid  = threadIdx.x;
    const int w    = tid >> 5;          // warp 0..3 == layer
    const int lane = tid & 31;
    const int g    = lane >> 2;         // MMA row base (this thread: rows g, g+8)
    const int t4   = lane & 3;          // thread-in-group (k-slice selector)
    const int odd  = t4 & 1;            // parity: 0 -> row g, 1 -> row g+8
    const int n    = (w << 2) | p;      // neuron; n/4 == w (layer)

    // ---- per-lane h1 weights ----
    const float* W1n = W1 + n * 96;     // (32,3); lane owns h1 row `lane`
    const float w10 = W1n[lane * 3 + 0];
    const float w11 = W1n[lane * 3 + 1];
    const float w12 = W1n[lane * 3 + 2];

    // ---- W2 as A-fragments for two m16n8k16 MMAs (k 0-15, 16-31) ----
    const float* W2n = W2 + n * 512;    // (16,32) row-major
    unsigned A1[4], A2[4];
    {
        const float* rg  = W2n + g * 32;
        const float* rg8 = W2n + (g + 8) * 32;
        const int c = 2 * t4;
        A1[0] = pack_h2(rg [c],      rg [c + 1]);
        A1[1] = pack_h2(rg8[c],      rg8[c + 1]);
        A1[2] = pack_h2(rg [c + 8],  rg [c + 9]);
        A1[3] = pack_h2(rg8[c + 8],  rg8[c + 9]);
        A2[0] = pack_h2(rg [c + 16], rg [c + 17]);
        A2[1] = pack_h2(rg8[c + 16], rg8[c + 17]);
        A2[2] = pack_h2(rg [c + 24], rg [c + 25]);
        A2[3] = pack_h2(rg8[c + 24], rg8[c + 25]);
    }
    const float c0i = b2[n * 16 + g];       // C-frag bias (rows g / g+8)
    const float c2i = b2[n * 16 + g + 8];
    // parity-selected row for this lane; 0.5: redux double-counts (2 copies)
    const int   rsel = odd ? g + 8 : g;
    const float w3sel = 0.5f * FIXSCALE * W3[n * 16 + rsel];

    const float b3n  = b3[n];
    const float Ev   = expf(logE[n]);
    const float etav = expf(logeta[n]);
    const float iwv  = 1.0f / (1.0f + expf(-imp[n]));
    const float Al   = w12 * iwv;              // prev-coupling, folded
    const float Al18 = Al * FIXINV;            // applied to the scaled sum
    const float iw18 = iwv * FIXINV;
    // biased-sum folds: consumer sees sumf_b = MAGICF + sum
    const float b1l2 = b1[n * 32 + lane] + Al * b3n - Al18 * MAGICF;
    const float b3iw = b3n * iwv - iw18 * MAGICF;
    const float csel = odd ? c2i : c0i;        // bias for the selected row

    // permuted fp16 slot so one LDS.128 returns both MMAs' B-fragments:
    // half-index = 8*((l>>1)&3) + 2*(l>>3) + (l&1)
    const int hidx = 8 * ((lane >> 1) & 3) + 2 * (lane >> 3) + (lane & 1);

    // ---- shared memory (tiny) ----
    __shared__ __align__(16) __half sh_hh[4][2][32]; // [warp][parity][slot]
    __shared__ __align__(16) float2 sh_x[2][32];     // double-buffered x window
    __shared__ float  sh_tr[2][4][32];               // [buf][layer][t] traces
    __shared__ float  a_sh[16][4];                   // mixing consts
    __shared__ float  wf2_sh[16];
    __shared__ float  bf1_sh[16];
    __shared__ float  bf2_sh;

    const float2* x2 = (const float2*)x;

    if (tid < 16) {
        const int f = tid;
        float mx = fmaxf(fmaxf(lw[0], lw[1]), fmaxf(lw[2], lw[3]));
        float e0 = expf(lw[0] - mx), e1 = expf(lw[1] - mx);
        float e2 = expf(lw[2] - mx), e3 = expf(lw[3] - mx);
        float es = e0 + e1 + e2 + e3;
        float wl[4] = { e0 / es, e1 / es, e2 / es, e3 / es };
#pragma unroll
        for (int l = 0; l < 4; l++) {
            float s = 0.0f;
#pragma unroll
            for (int pp = 0; pp < 4; pp++)
                s += 1.0f / (1.0f + expf(-imp[l * 4 + pp]));
            float S = s / (s + 1e-8f);
            a_sh[f][l] = Wf1[f * 4 + l] * (S * wl[l]);
        }
        wf2_sh[f] = Wf2[f];
        bf1_sh[f] = bf1[f];
        if (f == 0) bf2_sh = bf2[0];
    }
    if (tid < 32) sh_x[0][tid] = x2[b * TLEN + tid];   // stage first window
    __syncthreads();

    float sumf_b = MAGICF;  // biased carried sum (value = MAGICF + 0)
    float mprev  = -b3n;    // carried maxwell term; cancels folded Al*b3n at u=0
    float keep_s = MAGICF;  // kept biased sum for the lane's step

    for (int t0 = 0; t0 < TLEN; t0 += 32) {
        const int buf = (t0 >> 5) & 1;
        const float4* xw4 = (const float4*)&sh_x[buf][0];

#pragma unroll
        for (int v2i = 0; v2i < 16; v2i++) {        // 2 timesteps per iter
            float4 xx = xw4[v2i];                    // broadcast LDS.128
#pragma unroll
            for (int s = 0; s < 2; s++) {            // s == step parity
                const int   u      = 2 * v2i + s;
                const float strain = s ? xx.z : xx.x;
                const float rate   = s ? xx.w : xx.y;

                // off-path work (b3n and -Al18*MAGICF pre-folded into b1l2)
                float m  = fmaf(Ev, strain, etav * rate);
                float zo = fmaf(Al, mprev,
                                fmaf(w11, rate, fmaf(w10, strain, b1l2)));

                // ---- critical path: sumf_b -> z -> tanh -> exchange ->
                //      2x independent HMMA -> FADD -> tanh -> redux ----
                float h = tanh_mufu(fmaf(Al18, sumf_b, zo));

                sh_hh[w][s][hidx] = __float2half_rn(h);   // STS.16, permuted
                // no syncwarp: divergence-free warp => in-order LSU services
                // the store wavefront before the next load; WAR across steps
                // covered by the parity buffers.

                uint4 bb = *(const uint4*)&sh_hh[w][s][8 * t4]; // B frags
                float d0, d1, d2, d3;                // k 0-15, C = bias
                mma16816(d0, d1, d2, d3,
                         A1[0], A1[1], A1[2], A1[3], bb.x, bb.y,
                         csel, csel, csel, csel);
                float e0, e1, e2, e3;                // k 16-31, C = 0 (indep)
                mma16816(e0, e1, e2, e3,
                         A2[0], A2[1], A2[2], A2[3], bb.z, bb.w,
                         0.0f, 0.0f, 0.0f, 0.0f);

                // parity-selected row preact (bias already in d via csel)
                float dsel = odd ? (d2 + e2) : (d0 + e0);
                float h2v  = tanh_mufu(dsel);        // ONE tanh per lane

                // magic-bias fixed point; redux sums biases modularly
                int ib = __float_as_int(fmaf(w3sel, h2v, MAGICF));
                int is = __reduce_add_sync(0xffffffffu, ib);
                sumf_b = __int_as_float(is - BIAS_SUB);   // MAGICF + sum

                keep_s = (lane == u) ? sumf_b : keep_s;
                mprev  = m;
            }
        }

        // window epilogue: lane u recomputes its step's maxwell term from
        // its own staged x, reconstructs stress, dumps the trace.
        {
            float2 xl = sh_x[buf][lane];
            float ml  = fmaf(Ev, xl.x, etav * xl.y);
            float stress = fmaf(iw18, keep_s, fmaf(iwv, ml, b3iw));
            sh_tr[buf][w][lane] = stress;
        }
        if (w == 3 && t0 + 32 < TLEN)
            sh_x[buf ^ 1][lane] = x2[b * TLEN + t0 + 32 + lane];
        __syncthreads();

        // mixing head: warp 0, one t per lane
        if (w == 0) {
            float y0 = sh_tr[buf][0][lane];
            float y1 = sh_tr[buf][1][lane];
            float y2 = sh_tr[buf][2][lane];
            float y3 = sh_tr[buf][3][lane];
            float o = bf2_sh;
#pragma unroll
            for (int f = 0; f < 16; f++) {
                float hm = bf1_sh[f];
                hm = fmaf(a_sh[f][0], y0, hm);
                hm = fmaf(a_sh[f][1], y1, hm);
                hm = fmaf(a_sh[f][2], y2, hm);
                hm = fmaf(a_sh[f][3], y3, hm);
                o = fmaf(wf2_sh[f], fmaxf(hm, 0.0f), o);
            }
            out[p * BT + b * TLEN + t0 + lane] = o;
        }
        // sh_tr/sh_x double-buffered: next overwrite of each buffer is
        // separated by the NEXT window's __syncthreads.
    }
}

// ---------------------------------------------------------------------------
extern "C" void kernel_launch(void* const* d_in, const int* in_sizes, int n_in,
                              void* d_out, int out_size) {
    const float* x    = (const float*)d_in[0];
    const float* W1   = (const float*)d_in[1];
    const float* b1   = (const float*)d_in[2];
    const float* W2   = (const float*)d_in[3];
    const float* b2   = (const float*)d_in[4];
    const float* W3   = (const float*)d_in[5];
    const float* b3   = (const float*)d_in[6];
    const float* logE = (const float*)d_in[7];
    const float* loge = (const float*)d_in[8];
    const float* imp  = (const float*)d_in[9];
    const float* lw   = (const float*)d_in[10];
    const float* Wf1  = (const float*)d_in[11];
    const float* bf1  = (const float*)d_in[12];
    const float* Wf2  = (const float*)d_in[13];
    const float* bf2  = (const float*)d_in[14];
    float* out = (float*)d_out;

    pinn_fused_kernel<<<BATCH * 4, 128>>>(x, W1, b1, W2, b2, W3, b3,
                                          logE, loge, imp, lw, Wf1, bf1,
                                          Wf2, bf2, out);
}